// round 11
// baseline (speedup 1.0000x reference)
#include <cuda_runtime.h>
#include <cuda_fp16.h>
#include <math.h>
#include <stdint.h>

// ---------------- problem constants ----------------
#define B_    4
#define S_    2048
#define D_    2048
#define H_    16
#define DH_   128
#define DFF_  8192
#define MTOK  (B_*S_)          // 8192
#define D3_   (3*D_)           // 6144

// ---------------- scratch (device globals) ----------------
__device__ float   g_X    [(size_t)MTOK * D3_];       // QKV out fp32
__device__ float   g_WsmP [8][64][DH_*DH_];           // gram split-K partials
__device__ float   g_Wsm  [64][DH_*DH_];              // softmax(w)
__device__ float   g_R1   [(size_t)MTOK * D_];
__device__ float   g_LN1  [(size_t)MTOK * D_];        // LN1 fp32 (residual source)
__device__ float   g_R2   [(size_t)MTOK * D_];
__device__ __half  g_x16  [(size_t)MTOK * D_];
__device__ __half  g_W116 [(size_t)D3_  * D_];
__device__ __half  g_W216 [(size_t)D_   * D_];
__device__ __half  g_fc16 [(size_t)DFF_ * D_];
__device__ __half  g_pj16 [(size_t)D_   * DFF_];
__device__ __half  g_A16  [(size_t)MTOK * D_];
__device__ __half  g_L116 [(size_t)MTOK * D_];
__device__ __half  g_H16  [(size_t)MTOK * DFF_];
__device__ double  g_part [2048];
__device__ float   g_stats[2];

__device__ __forceinline__ float gelu_f(float x) {
    float x3 = x * x * x;
    return 0.5f * x * (1.0f + tanhf(0.7978845608028654f * (x + 0.044715f * x3)));
}

// ================= baseline-PTX helpers =================
__device__ __forceinline__ uint32_t smem_u32(const void* p) {
    uint32_t a;
    asm("{ .reg .u64 t; cvta.to.shared.u64 t, %1; cvt.u32.u64 %0, t; }" : "=r"(a) : "l"(p));
    return a;
}
__device__ __forceinline__ void cp16(uint32_t s, const void* g) {
    asm volatile("cp.async.cg.shared.global [%0], [%1], 16;" :: "r"(s), "l"(g));
}
#define CP_COMMIT() asm volatile("cp.async.commit_group;" ::: "memory")
template<int N> __device__ __forceinline__ void cp_wait() {
    asm volatile("cp.async.wait_group %0;" :: "n"(N) : "memory");
}
__device__ __forceinline__ uint32_t swz128(uint32_t off) { return off ^ ((off >> 3) & 0x70); }

#define LDSM4(r, addr) \
    asm volatile("ldmatrix.sync.aligned.m8n8.x4.shared.b16 {%0,%1,%2,%3}, [%4];" \
        : "=r"((r)[0]), "=r"((r)[1]), "=r"((r)[2]), "=r"((r)[3]) : "r"(addr))

#define MMA16816(c, a, b0, b1) \
    asm volatile("mma.sync.aligned.m16n8k16.row.col.f32.f16.f16.f32 " \
        "{%0,%1,%2,%3},{%4,%5,%6,%7},{%8,%9},{%0,%1,%2,%3};" \
        : "+f"((c)[0]), "+f"((c)[1]), "+f"((c)[2]), "+f"((c)[3]) \
        : "r"((a)[0]), "r"((a)[1]), "r"((a)[2]), "r"((a)[3]), "r"(b0), "r"(b1))

// ================= mma.sync GEMM: C[M,N] = A[M,K]f16 @ B[N,K]f16^T ======
// CTA tile 128x128, K-step 64, 3-stage cp.async pipeline.
// 128 threads = 4 warps (2M x 2N), warp tile 64x64 -> 4 LDSM per 16 MMAs.
// 2 CTAs/SM, two independent sync domains.
#define NS          3
#define STAGE_BYTES 32768            // A 128x64x2 = 16K, B 128x64x2 = 16K
#define TCG_SMEM    (NS * STAGE_BYTES)

__device__ __forceinline__ void load_tile(
    const __half* __restrict__ A, const __half* __restrict__ Bw,
    uint32_t tA, uint32_t tB, long long ldg, long long k0, int tid)
{
    #pragma unroll
    for (int i = 0; i < 8; i++) {                       // A: 1024 x 16B chunks
        int q = tid + 128 * i; int r = q >> 3, c = q & 7;
        cp16(tA + swz128(r * 128 + c * 16), A + r * ldg + k0 + c * 8);
    }
    #pragma unroll
    for (int i = 0; i < 8; i++) {                       // B: 1024 x 16B chunks
        int q = tid + 128 * i; int r = q >> 3, c = q & 7;
        cp16(tB + swz128(r * 128 + c * 16), Bw + r * ldg + k0 + c * 8);
    }
}

// RES: add fp32 residual. H16: write fp16 copy. STATS: per-CTA LN partials.
template<bool GELU, bool RES, bool H16, bool STATS>
__global__ __launch_bounds__(128, 2) void mma_gemm(
    const __half* __restrict__ A, const __half* __restrict__ Bw,
    int K, const float* __restrict__ bias, const float* __restrict__ residf,
    float* __restrict__ Cf, __half* __restrict__ C16, int N)
{
    extern __shared__ char smem[];
    const uint32_t tiles = smem_u32(smem);
    const int tid  = threadIdx.x;
    const int wid  = tid >> 5, lane = tid & 31;
    const int wm   = wid >> 1, wn = wid & 1;            // 2 x 2 warp grid, 64x64 tiles

    const long long rowA0 = (long long)blockIdx.y * 128;
    const long long rowB0 = (long long)blockIdx.x * 128;
    const int total = K >> 6;

    float acc[4][8][4];
    #pragma unroll
    for (int i = 0; i < 4; i++)
        #pragma unroll
        for (int j = 0; j < 8; j++)
            #pragma unroll
            for (int q = 0; q < 4; q++) acc[i][j][q] = 0.0f;

    const __half* Ap = A + rowA0 * K;
    const __half* Bp = Bw + rowB0 * K;

    for (int s = 0; s < 2; s++) {
        load_tile(Ap, Bp, tiles + s * STAGE_BYTES, tiles + s * STAGE_BYTES + 16384,
                  K, (long long)s << 6, tid);
        CP_COMMIT();
    }

    for (int m = 0; m < total; m++) {
        cp_wait<1>();
        __syncthreads();
        const int s = m + 2;
        if (s < total) {
            const int slot = s % NS;
            load_tile(Ap, Bp, tiles + slot * STAGE_BYTES, tiles + slot * STAGE_BYTES + 16384,
                      K, (long long)s << 6, tid);
        }
        CP_COMMIT();

        const uint32_t Asm = tiles + (m % NS) * STAGE_BYTES;
        const uint32_t Bsm = Asm + 16384;
        #pragma unroll
        for (int kk = 0; kk < 4; kk++) {
            uint32_t af[4][4];
            #pragma unroll
            for (int mi = 0; mi < 4; mi++) {
                uint32_t addr = Asm + swz128((wm * 64 + mi * 16 + (lane & 15)) * 128
                                             + kk * 32 + (lane >> 4) * 16);
                LDSM4(af[mi], addr);
            }
            uint32_t bfr[4][4];
            #pragma unroll
            for (int nj = 0; nj < 4; nj++) {
                uint32_t addr = Bsm + swz128((wn * 64 + nj * 16 + (lane & 15)) * 128
                                             + kk * 32 + (lane >> 4) * 16);
                LDSM4(bfr[nj], addr);
            }
            #pragma unroll
            for (int mi = 0; mi < 4; mi++)
                #pragma unroll
                for (int nj = 0; nj < 4; nj++) {
                    MMA16816(acc[mi][2*nj],   af[mi], bfr[nj][0], bfr[nj][2]);
                    MMA16816(acc[mi][2*nj+1], af[mi], bfr[nj][1], bfr[nj][3]);
                }
        }
    }

    // ---------------- epilogue ----------------
    float st_s = 0.0f, st_q = 0.0f;
    const long long rowT = rowA0 + wm * 64;
    const long long colT = rowB0 + wn * 64;
    #pragma unroll
    for (int mi = 0; mi < 4; mi++) {
        #pragma unroll
        for (int n8 = 0; n8 < 8; n8++) {
            const long long col = colT + n8 * 8 + (lane & 3) * 2;
            const float b0 = bias[col], b1 = bias[col + 1];
            #pragma unroll
            for (int h = 0; h < 2; h++) {
                const long long row = rowT + mi * 16 + (lane >> 2) + h * 8;
                float v0 = acc[mi][n8][2*h]     + b0;
                float v1 = acc[mi][n8][2*h + 1] + b1;
                if (RES) {
                    const float2 rv = *(const float2*)(residf + row * N + col);
                    v0 += rv.x; v1 += rv.y;
                }
                if (GELU) { v0 = gelu_f(v0); v1 = gelu_f(v1); }
                if (STATS) { st_s += v0 + v1; st_q += v0 * v0 + v1 * v1; }
                if (H16) {
                    *(__half2*)(C16 + row * N + col) =
                        __halves2half2(__float2half(v0), __float2half(v1));
                }
                if (Cf != nullptr) {
                    *(float2*)(Cf + row * N + col) = make_float2(v0, v1);
                }
            }
        }
    }
    if (STATS) {
        __syncthreads();
        double* shs = (double*)smem;
        double* shq = shs + 128;
        shs[tid] = (double)st_s; shq[tid] = (double)st_q;
        __syncthreads();
        for (int off = 64; off; off >>= 1) {
            if (tid < off) { shs[tid] += shs[tid + off]; shq[tid] += shq[tid + off]; }
            __syncthreads();
        }
        if (tid == 0) {
            int cta = blockIdx.y * gridDim.x + blockIdx.x;
            g_part[2 * cta] = shs[0];
            g_part[2 * cta + 1] = shq[0];
        }
    }
}

// ================= fp32 -> fp16 conversion =================
__global__ void convert_h(const float* __restrict__ src, __half* __restrict__ dst, long long n)
{
    for (long long i = ((long long)blockIdx.x * blockDim.x + threadIdx.x) * 4; i < n;
         i += (long long)gridDim.x * blockDim.x * 4) {
        float4 v = *(const float4*)(src + i);
        *(__half2*)(dst + i)     = __halves2half2(__float2half(v.x), __float2half(v.y));
        *(__half2*)(dst + i + 2) = __halves2half2(__float2half(v.z), __float2half(v.w));
    }
}

// ================= SIMT pieces (round-7 proven) =================
#define BN 128

// A = w @ V^T per (b,h); writes fp16 directly
__global__ __launch_bounds__(256) void wvT_kernel(const float* __restrict__ Wsm,
                                                  const float* __restrict__ X,
                                                  __half* __restrict__ C16)
{
    int z = blockIdx.z; int b = z >> 4; int h = z & 15;
    const float* Ap = Wsm + (long long)z * (DH_ * DH_);
    const float* Bp = X + (long long)b * S_ * D3_ + 2 * D_ + (long long)h * DH_;
    __half* Cp = C16 + ((long long)b * S_ + (long long)h * DH_) * D_;

    __shared__ float As[16][128 + 4];
    __shared__ float Bs[16][BN + 4];
    int tid = threadIdx.x, tx = tid & 15, ty = tid >> 4;
    long long colBase = (long long)blockIdx.x * BN;
    int lr = tid >> 2, lc = (tid & 3) << 2;
    const float* Aload = Ap + lr * DH_ + lc;
    const float* Bload = Bp + (colBase + lr) * (long long)D3_ + lc;

    float acc[8][8];
    #pragma unroll
    for (int i = 0; i < 8; i++) {
        #pragma unroll
        for (int j = 0; j < 8; j++) acc[i][j] = 0.0f;
    }

    for (int k0 = 0; k0 < DH_; k0 += 16) {
        float4 a0 = *(const float4*)(Aload + k0);
        float4 a1 = *(const float4*)(Aload + 64 * DH_ + k0);
        float4 b0 = *(const float4*)(Bload + k0);
        float4 b1 = *(const float4*)(Bload + 64LL * D3_ + k0);
        __syncthreads();
        As[lc+0][lr] = a0.x; As[lc+1][lr] = a0.y; As[lc+2][lr] = a0.z; As[lc+3][lr] = a0.w;
        As[lc+0][lr+64] = a1.x; As[lc+1][lr+64] = a1.y; As[lc+2][lr+64] = a1.z; As[lc+3][lr+64] = a1.w;
        Bs[lc+0][lr] = b0.x; Bs[lc+1][lr] = b0.y; Bs[lc+2][lr] = b0.z; Bs[lc+3][lr] = b0.w;
        Bs[lc+0][lr+64] = b1.x; Bs[lc+1][lr+64] = b1.y; Bs[lc+2][lr+64] = b1.z; Bs[lc+3][lr+64] = b1.w;
        __syncthreads();
        #pragma unroll
        for (int kk = 0; kk < 16; kk++) {
            float4 av0 = *(const float4*)&As[kk][ty * 8];
            float4 av1 = *(const float4*)&As[kk][ty * 8 + 4];
            float4 bv0 = *(const float4*)&Bs[kk][tx * 8];
            float4 bv1 = *(const float4*)&Bs[kk][tx * 8 + 4];
            float a[8] = {av0.x, av0.y, av0.z, av0.w, av1.x, av1.y, av1.z, av1.w};
            float bb[8] = {bv0.x, bv0.y, bv0.z, bv0.w, bv1.x, bv1.y, bv1.z, bv1.w};
            #pragma unroll
            for (int i = 0; i < 8; i++)
                #pragma unroll
                for (int j = 0; j < 8; j++) acc[i][j] += a[i] * bb[j];
        }
    }
    #pragma unroll
    for (int i = 0; i < 8; i++) {
        long long rbase = (long long)(ty * 8 + i) * D_ + colBase + tx * 8;
        #pragma unroll
        for (int j = 0; j < 8; j += 2) {
            *(__half2*)(Cp + rbase + j) =
                __halves2half2(__float2half(acc[i][j]), __float2half(acc[i][j+1]));
        }
    }
}

__global__ __launch_bounds__(256) void attn_gram_kernel()
{
    int z = blockIdx.x, split = blockIdx.y;
    int b = z >> 4, h = z & 15;
    const float* Qb = g_X + (long long)b * S_ * D3_ + (long long)h * DH_;
    const float* Kb = Qb + D_;
    __shared__ float Qs[32][DH_];
    __shared__ float Ks[32][DH_];
    int tid = threadIdx.x, tx = tid & 15, ty = tid >> 4;
    int r = tid >> 3, c = (tid & 7) << 4;
    float acc[8][8];
    #pragma unroll
    for (int i = 0; i < 8; i++) {
        #pragma unroll
        for (int j = 0; j < 8; j++) acc[i][j] = 0.0f;
    }
    int s_begin = split * 256;
    for (int s0 = s_begin; s0 < s_begin + 256; s0 += 32) {
        __syncthreads();
        long long rowOff = (long long)(s0 + r) * D3_;
        #pragma unroll
        for (int i = 0; i < 4; i++) {
            *(float4*)&Qs[r][c + 4*i] = *(const float4*)&Qb[rowOff + c + 4*i];
            *(float4*)&Ks[r][c + 4*i] = *(const float4*)&Kb[rowOff + c + 4*i];
        }
        __syncthreads();
        #pragma unroll
        for (int kk = 0; kk < 32; kk++) {
            float4 av0 = *(const float4*)&Qs[kk][ty*8];
            float4 av1 = *(const float4*)&Qs[kk][ty*8+4];
            float4 bv0 = *(const float4*)&Ks[kk][tx*8];
            float4 bv1 = *(const float4*)&Ks[kk][tx*8+4];
            float a[8] = {av0.x,av0.y,av0.z,av0.w,av1.x,av1.y,av1.z,av1.w};
            float bb[8] = {bv0.x,bv0.y,bv0.z,bv0.w,bv1.x,bv1.y,bv1.z,bv1.w};
            #pragma unroll
            for (int i = 0; i < 8; i++)
                #pragma unroll
                for (int j = 0; j < 8; j++) acc[i][j] += a[i] * bb[j];
        }
    }
    #pragma unroll
    for (int i = 0; i < 8; i++) {
        int d = ty * 8 + i;
        *(float4*)&g_WsmP[split][z][d*DH_ + tx*8]   = make_float4(acc[i][0],acc[i][1],acc[i][2],acc[i][3]);
        *(float4*)&g_WsmP[split][z][d*DH_ + tx*8+4] = make_float4(acc[i][4],acc[i][5],acc[i][6],acc[i][7]);
    }
}

__global__ void softmax_kernel()
{
    int row = blockIdx.x;
    int z = row >> 7, d = row & 127;
    int e = threadIdx.x;
    float v = 0.0f;
    #pragma unroll
    for (int p = 0; p < 8; p++) v += g_WsmP[p][z][d*DH_ + e];
    v *= 0.022097086912079608f;
    __shared__ float red[128];
    red[e] = v; __syncthreads();
    for (int off = 64; off; off >>= 1) { if (e < off) red[e] = fmaxf(red[e], red[e+off]); __syncthreads(); }
    float mx = red[0];
    __syncthreads();
    float ex = expf(v - mx);
    red[e] = ex; __syncthreads();
    for (int off = 64; off; off >>= 1) { if (e < off) red[e] += red[e+off]; __syncthreads(); }
    g_Wsm[z][d*DH_ + e] = ex / red[0];
}

// finalize mean / inv_std from per-CTA partials
__global__ void reduce2_kernel(double n, int nparts)
{
    int t = threadIdx.x;
    double s = 0.0, ss = 0.0;
    for (int i = t; i < nparts; i += 256) { s += g_part[2*i]; ss += g_part[2*i+1]; }
    __shared__ double shs[256], shq[256];
    shs[t] = s; shq[t] = ss; __syncthreads();
    for (int off = 128; off; off >>= 1) {
        if (t < off) { shs[t] += shs[t+off]; shq[t] += shq[t+off]; }
        __syncthreads();
    }
    if (t == 0) {
        double mean = shs[0] / n;
        double var  = (shq[0] - n * mean * mean) / (n - 1.0);
        g_stats[0] = (float)mean;
        g_stats[1] = (float)(1.0 / sqrt(var + 1e-12));
    }
}

// LN apply -> fp16 operand + fp32 residual copy
__global__ void ln_apply_dual_kernel(const float* __restrict__ x, const float* __restrict__ w,
                                     const float* __restrict__ bb, __half* __restrict__ y16,
                                     float* __restrict__ yf, long long n)
{
    float mean = g_stats[0], inv = g_stats[1];
    for (long long i = (long long)blockIdx.x * blockDim.x + threadIdx.x; i < n;
         i += (long long)gridDim.x * blockDim.x) {
        int col = (int)(i & (D_ - 1));
        float v = (x[i] - mean) * inv * w[col] + bb[col];
        y16[i] = __float2half(v);
        yf[i]  = v;
    }
}

// LN apply -> fp32 (final output)
__global__ void ln_apply_f_kernel(const float* __restrict__ x, const float* __restrict__ w,
                                  const float* __restrict__ bb, float* __restrict__ y, long long n)
{
    float mean = g_stats[0], inv = g_stats[1];
    for (long long i = (long long)blockIdx.x * blockDim.x + threadIdx.x; i < n;
         i += (long long)gridDim.x * blockDim.x) {
        int col = (int)(i & (D_ - 1));
        y[i] = (x[i] - mean) * inv * w[col] + bb[col];
    }
}

// ================= launcher =================
extern "C" void kernel_launch(void* const* d_in, const int* in_sizes, int n_in,
                              void* d_out, int out_size)
{
    const float* x      = (const float*)d_in[0];
    const float* W1_w   = (const float*)d_in[1];
    const float* W1_b   = (const float*)d_in[2];
    const float* W2_w   = (const float*)d_in[3];
    const float* W2_b   = (const float*)d_in[4];
    const float* fc_w   = (const float*)d_in[5];
    const float* fc_b   = (const float*)d_in[6];
    const float* proj_w = (const float*)d_in[7];
    const float* proj_b = (const float*)d_in[8];
    const float* ln1_w  = (const float*)d_in[9];
    const float* ln1_b  = (const float*)d_in[10];
    const float* ln2_w  = (const float*)d_in[11];
    const float* ln2_b  = (const float*)d_in[12];
    float* out = (float*)d_out;

    float *pX, *pWsm, *pR1, *pLN1, *pR2;
    __half *px16, *pW116, *pW216, *pfc16, *ppj16, *pA16, *pL116, *pH16;
    cudaGetSymbolAddress((void**)&pX,    g_X);
    cudaGetSymbolAddress((void**)&pWsm,  g_Wsm);
    cudaGetSymbolAddress((void**)&pR1,   g_R1);
    cudaGetSymbolAddress((void**)&pLN1,  g_LN1);
    cudaGetSymbolAddress((void**)&pR2,   g_R2);
    cudaGetSymbolAddress((void**)&px16,  g_x16);
    cudaGetSymbolAddress((void**)&pW116, g_W116);
    cudaGetSymbolAddress((void**)&pW216, g_W216);
    cudaGetSymbolAddress((void**)&pfc16, g_fc16);
    cudaGetSymbolAddress((void**)&ppj16, g_pj16);
    cudaGetSymbolAddress((void**)&pA16,  g_A16);
    cudaGetSymbolAddress((void**)&pL116, g_L116);
    cudaGetSymbolAddress((void**)&pH16,  g_H16);

    cudaFuncSetAttribute(mma_gemm<false,false,false,false>, cudaFuncAttributeMaxDynamicSharedMemorySize, TCG_SMEM);
    cudaFuncSetAttribute(mma_gemm<false,true ,false,true >, cudaFuncAttributeMaxDynamicSharedMemorySize, TCG_SMEM);
    cudaFuncSetAttribute(mma_gemm<true ,false,true ,false>, cudaFuncAttributeMaxDynamicSharedMemorySize, TCG_SMEM);

    const long long nLN = (long long)MTOK * D_;

    // 0) conversions to fp16
    convert_h<<<2048, 256>>>(x,      px16,  (long long)MTOK * D_);
    convert_h<<<2048, 256>>>(W1_w,   pW116, (long long)D3_  * D_);
    convert_h<<<1024, 256>>>(W2_w,   pW216, (long long)D_   * D_);
    convert_h<<<2048, 256>>>(fc_w,   pfc16, (long long)DFF_ * D_);
    convert_h<<<2048, 256>>>(proj_w, ppj16, (long long)D_ * DFF_);

    // 1) QKV: g_X = x @ W1^T + b          [8192,6144] fp32
    mma_gemm<false,false,false,false><<<dim3(D3_/128, MTOK/128), 128, TCG_SMEM>>>(
        px16, pW116, D_, W1_b, nullptr, pX, nullptr, D3_);

    // 2-3) gram + softmax
    attn_gram_kernel<<<dim3(64, 8), 256>>>();
    softmax_kernel<<<64 * DH_, 128>>>();

    // 4) A = w @ V^T -> fp16 directly
    wvT_kernel<<<dim3(D_/BN, 1, 64), 256>>>(pWsm, pX, pA16);

    // 5) R1 = A @ W2^T + b + x   (fp32 resid; emits LN partials; 1024 CTAs)
    mma_gemm<false,true,false,true><<<dim3(D_/128, MTOK/128), 128, TCG_SMEM>>>(
        pA16, pW216, D_, W2_b, x, pR1, nullptr, D_);

    // 6) LN1: finalize stats; apply -> fp16 operand + fp32 residual
    reduce2_kernel<<<1, 256>>>((double)nLN, (D_/128) * (MTOK/128));
    ln_apply_dual_kernel<<<8192, 256>>>(pR1, ln1_w, ln1_b, pL116, pLN1, nLN);

    // 7) H16 = fp16(gelu(LN1 @ fc^T + b))   [8192,8192]
    mma_gemm<true,false,true,false><<<dim3(DFF_/128, MTOK/128), 128, TCG_SMEM>>>(
        pL116, pfc16, D_, fc_b, nullptr, nullptr, pH16, DFF_);

    // 8) R2 = H @ proj^T + b + LN1  (fp32 resid; emits LN partials)
    mma_gemm<false,true,false,true><<<dim3(D_/128, MTOK/128), 128, TCG_SMEM>>>(
        pH16, ppj16, DFF_, proj_b, pLN1, pR2, nullptr, D_);

    // 9) LN2 -> out
    reduce2_kernel<<<1, 256>>>((double)nLN, (D_/128) * (MTOK/128));
    ln_apply_f_kernel<<<8192, 256>>>(pR2, ln2_w, ln2_b, out, nLN);
}

// round 12
// speedup vs baseline: 1.1336x; 1.1336x over previous
#include <cuda_runtime.h>
#include <cuda_fp16.h>
#include <math.h>
#include <stdint.h>

// ---------------- problem constants ----------------
#define B_    4
#define S_    2048
#define D_    2048
#define H_    16
#define DH_   128
#define DFF_  8192
#define MTOK  (B_*S_)          // 8192
#define D3_   (3*D_)           // 6144

// ---------------- scratch (device globals) ----------------
__device__ float   g_X    [(size_t)MTOK * D3_];       // QKV out fp32
__device__ float   g_WsmP [8][64][DH_*DH_];           // gram split-K partials
__device__ float   g_Wsm  [64][DH_*DH_];              // softmax(w)
__device__ float   g_R1   [(size_t)MTOK * D_];
__device__ float   g_LN1  [(size_t)MTOK * D_];        // LN1 fp32 (residual source)
__device__ float   g_R2   [(size_t)MTOK * D_];
__device__ __half  g_x16  [(size_t)MTOK * D_];
__device__ __half  g_W116 [(size_t)D3_  * D_];
__device__ __half  g_W216 [(size_t)D_   * D_];
__device__ __half  g_fc16 [(size_t)DFF_ * D_];
__device__ __half  g_pj16 [(size_t)D_   * DFF_];
__device__ __half  g_A16  [(size_t)MTOK * D_];
__device__ __half  g_L116 [(size_t)MTOK * D_];
__device__ __half  g_H16  [(size_t)MTOK * DFF_];
__device__ double  g_part [2048];
__device__ float   g_stats[2];

// gelu with HW tanh.approx.f32 (sm_75+): max tanh err ~6e-4, then fp16-rounded — safe.
__device__ __forceinline__ float gelu_f(float x) {
    float u = 0.7978845608028654f * (x + 0.044715f * x * x * x);
    float t;
    asm("tanh.approx.f32 %0, %1;" : "=f"(t) : "f"(u));
    return 0.5f * x * (1.0f + t);
}

// ================= baseline-PTX helpers =================
__device__ __forceinline__ uint32_t smem_u32(const void* p) {
    uint32_t a;
    asm("{ .reg .u64 t; cvta.to.shared.u64 t, %1; cvt.u32.u64 %0, t; }" : "=r"(a) : "l"(p));
    return a;
}
__device__ __forceinline__ void cp16(uint32_t s, const void* g) {
    asm volatile("cp.async.cg.shared.global [%0], [%1], 16;" :: "r"(s), "l"(g));
}
#define CP_COMMIT() asm volatile("cp.async.commit_group;" ::: "memory")
template<int N> __device__ __forceinline__ void cp_wait() {
    asm volatile("cp.async.wait_group %0;" :: "n"(N) : "memory");
}
__device__ __forceinline__ uint32_t swz128(uint32_t off) { return off ^ ((off >> 3) & 0x70); }

#define LDSM4(r, addr) \
    asm volatile("ldmatrix.sync.aligned.m8n8.x4.shared.b16 {%0,%1,%2,%3}, [%4];" \
        : "=r"((r)[0]), "=r"((r)[1]), "=r"((r)[2]), "=r"((r)[3]) : "r"(addr))

#define MMA16816(c, a, b0, b1) \
    asm volatile("mma.sync.aligned.m16n8k16.row.col.f32.f16.f16.f32 " \
        "{%0,%1,%2,%3},{%4,%5,%6,%7},{%8,%9},{%0,%1,%2,%3};" \
        : "+f"((c)[0]), "+f"((c)[1]), "+f"((c)[2]), "+f"((c)[3]) \
        : "r"((a)[0]), "r"((a)[1]), "r"((a)[2]), "r"((a)[3]), "r"(b0), "r"(b1))

// ================= mma.sync GEMM: C[M,N] = A[M,K]f16 @ B[N,K]f16^T ======
// Tile 128x128, K-step 64, 3-stage cp.async pipeline, 8 warps (4M x 2N), warp tile 32x64.
// 2 CTAs/SM. (round-7 proven config)
#define NS          3
#define STAGE_BYTES 32768            // A 128x64x2 = 16K, B 128x64x2 = 16K
#define TCG_SMEM    (NS * STAGE_BYTES)

__device__ __forceinline__ void load_tile(
    const __half* __restrict__ A, const __half* __restrict__ Bw,
    uint32_t tA, uint32_t tB, long long rowA0, long long rowB0,
    long long ldg, long long k0, int tid)
{
    #pragma unroll
    for (int i = 0; i < 4; i++) {                       // A: 1024 x 16B chunks
        int q = tid + 256 * i; int r = q >> 3, c = q & 7;
        cp16(tA + swz128(r * 128 + c * 16), A + (rowA0 + r) * ldg + k0 + c * 8);
    }
    #pragma unroll
    for (int i = 0; i < 4; i++) {                       // B: 1024 x 16B chunks
        int q = tid + 256 * i; int r = q >> 3, c = q & 7;
        cp16(tB + swz128(r * 128 + c * 16), Bw + (rowB0 + r) * ldg + k0 + c * 8);
    }
}

// RES: add fp32 residual. H16: also write fp16 copy of output. STATS: per-CTA LN partials.
template<bool GELU, bool RES, bool H16, bool STATS>
__global__ __launch_bounds__(256, 2) void mma_gemm(
    const __half* __restrict__ A, const __half* __restrict__ Bw,
    int K, const float* __restrict__ bias, const float* __restrict__ residf,
    float* __restrict__ Cf, __half* __restrict__ C16, int N)
{
    extern __shared__ char smem[];
    const uint32_t tiles = smem_u32(smem);
    const int tid  = threadIdx.x;
    const int wid  = tid >> 5, lane = tid & 31;
    const int wm   = wid >> 1, wn = wid & 1;            // 4 M x 2 N warp grid

    const long long ldg   = K;
    const long long rowA0 = (long long)blockIdx.y * 128;
    const long long rowB0 = (long long)blockIdx.x * 128;
    const int total = K >> 6;

    float acc[2][8][4];
    #pragma unroll
    for (int i = 0; i < 2; i++)
        #pragma unroll
        for (int j = 0; j < 8; j++)
            #pragma unroll
            for (int q = 0; q < 4; q++) acc[i][j][q] = 0.0f;

    for (int s = 0; s < 2; s++) {
        load_tile(A, Bw, tiles + s * STAGE_BYTES, tiles + s * STAGE_BYTES + 16384,
                  rowA0, rowB0, ldg, (long long)s << 6, tid);
        CP_COMMIT();
    }

    for (int m = 0; m < total; m++) {
        cp_wait<1>();
        __syncthreads();
        const int s = m + 2;
        if (s < total) {
            const int slot = s % NS;
            load_tile(A, Bw, tiles + slot * STAGE_BYTES, tiles + slot * STAGE_BYTES + 16384,
                      rowA0, rowB0, ldg, (long long)s << 6, tid);
        }
        CP_COMMIT();

        const uint32_t Asm = tiles + (m % NS) * STAGE_BYTES;
        const uint32_t Bsm = Asm + 16384;
        #pragma unroll
        for (int kk = 0; kk < 4; kk++) {
            uint32_t af[2][4];
            #pragma unroll
            for (int mi = 0; mi < 2; mi++) {
                uint32_t addr = Asm + swz128((wm * 32 + mi * 16 + (lane & 15)) * 128
                                             + kk * 32 + (lane >> 4) * 16);
                LDSM4(af[mi], addr);
            }
            uint32_t bfr[4][4];
            #pragma unroll
            for (int nj = 0; nj < 4; nj++) {
                uint32_t addr = Bsm + swz128((wn * 64 + nj * 16 + (lane & 15)) * 128
                                             + kk * 32 + (lane >> 4) * 16);
                LDSM4(bfr[nj], addr);
            }
            #pragma unroll
            for (int mi = 0; mi < 2; mi++)
                #pragma unroll
                for (int nj = 0; nj < 4; nj++) {
                    MMA16816(acc[mi][2*nj],   af[mi], bfr[nj][0], bfr[nj][2]);
                    MMA16816(acc[mi][2*nj+1], af[mi], bfr[nj][1], bfr[nj][3]);
                }
        }
        __syncthreads();
    }

    // ---------------- epilogue ----------------
    float st_s = 0.0f, st_q = 0.0f;
    const long long rowT = rowA0 + wm * 32;
    const long long colT = rowB0 + wn * 64;
    #pragma unroll
    for (int mi = 0; mi < 2; mi++) {
        #pragma unroll
        for (int n8 = 0; n8 < 8; n8++) {
            const long long col = colT + n8 * 8 + (lane & 3) * 2;
            const float b0 = bias[col], b1 = bias[col + 1];
            #pragma unroll
            for (int h = 0; h < 2; h++) {
                const long long row = rowT + mi * 16 + (lane >> 2) + h * 8;
                float v0 = acc[mi][n8][2*h]     + b0;
                float v1 = acc[mi][n8][2*h + 1] + b1;
                if (RES) {
                    const float2 rv = *(const float2*)(residf + row * N + col);
                    v0 += rv.x; v1 += rv.y;
                }
                if (GELU) { v0 = gelu_f(v0); v1 = gelu_f(v1); }
                if (STATS) { st_s += v0 + v1; st_q += v0 * v0 + v1 * v1; }
                if (H16) {
                    *(__half2*)(C16 + row * N + col) =
                        __halves2half2(__float2half(v0), __float2half(v1));
                }
                if (Cf != nullptr) {
                    *(float2*)(Cf + row * N + col) = make_float2(v0, v1);
                }
            }
        }
    }
    if (STATS) {
        __syncthreads();
        double* shs = (double*)smem;
        double* shq = shs + 256;
        shs[tid] = (double)st_s; shq[tid] = (double)st_q;
        __syncthreads();
        for (int off = 128; off; off >>= 1) {
            if (tid < off) { shs[tid] += shs[tid + off]; shq[tid] += shq[tid + off]; }
            __syncthreads();
        }
        if (tid == 0) {
            int cta = blockIdx.y * gridDim.x + blockIdx.x;
            g_part[2 * cta] = shs[0];
            g_part[2 * cta + 1] = shq[0];
        }
    }
}

// ================= fp32 -> fp16 conversion =================
__global__ void convert_h(const float* __restrict__ src, __half* __restrict__ dst, long long n)
{
    for (long long i = ((long long)blockIdx.x * blockDim.x + threadIdx.x) * 4; i < n;
         i += (long long)gridDim.x * blockDim.x * 4) {
        float4 v = *(const float4*)(src + i);
        *(__half2*)(dst + i)     = __halves2half2(__float2half(v.x), __float2half(v.y));
        *(__half2*)(dst + i + 2) = __halves2half2(__float2half(v.z), __float2half(v.w));
    }
}

// ================= SIMT pieces (round-7 proven) =================
#define BN 128

// A = w @ V^T per (b,h); writes fp16 directly
__global__ __launch_bounds__(256) void wvT_kernel(const float* __restrict__ Wsm,
                                                  const float* __restrict__ X,
                                                  __half* __restrict__ C16)
{
    int z = blockIdx.z; int b = z >> 4; int h = z & 15;
    const float* Ap = Wsm + (long long)z * (DH_ * DH_);
    const float* Bp = X + (long long)b * S_ * D3_ + 2 * D_ + (long long)h * DH_;
    __half* Cp = C16 + ((long long)b * S_ + (long long)h * DH_) * D_;

    __shared__ float As[16][128 + 4];
    __shared__ float Bs[16][BN + 4];
    int tid = threadIdx.x, tx = tid & 15, ty = tid >> 4;
    long long colBase = (long long)blockIdx.x * BN;
    int lr = tid >> 2, lc = (tid & 3) << 2;
    const float* Aload = Ap + lr * DH_ + lc;
    const float* Bload = Bp + (colBase + lr) * (long long)D3_ + lc;

    float acc[8][8];
    #pragma unroll
    for (int i = 0; i < 8; i++) {
        #pragma unroll
        for (int j = 0; j < 8; j++) acc[i][j] = 0.0f;
    }

    for (int k0 = 0; k0 < DH_; k0 += 16) {
        float4 a0 = *(const float4*)(Aload + k0);
        float4 a1 = *(const float4*)(Aload + 64 * DH_ + k0);
        float4 b0 = *(const float4*)(Bload + k0);
        float4 b1 = *(const float4*)(Bload + 64LL * D3_ + k0);
        __syncthreads();
        As[lc+0][lr] = a0.x; As[lc+1][lr] = a0.y; As[lc+2][lr] = a0.z; As[lc+3][lr] = a0.w;
        As[lc+0][lr+64] = a1.x; As[lc+1][lr+64] = a1.y; As[lc+2][lr+64] = a1.z; As[lc+3][lr+64] = a1.w;
        Bs[lc+0][lr] = b0.x; Bs[lc+1][lr] = b0.y; Bs[lc+2][lr] = b0.z; Bs[lc+3][lr] = b0.w;
        Bs[lc+0][lr+64] = b1.x; Bs[lc+1][lr+64] = b1.y; Bs[lc+2][lr+64] = b1.z; Bs[lc+3][lr+64] = b1.w;
        __syncthreads();
        #pragma unroll
        for (int kk = 0; kk < 16; kk++) {
            float4 av0 = *(const float4*)&As[kk][ty * 8];
            float4 av1 = *(const float4*)&As[kk][ty * 8 + 4];
            float4 bv0 = *(const float4*)&Bs[kk][tx * 8];
            float4 bv1 = *(const float4*)&Bs[kk][tx * 8 + 4];
            float a[8] = {av0.x, av0.y, av0.z, av0.w, av1.x, av1.y, av1.z, av1.w};
            float bb[8] = {bv0.x, bv0.y, bv0.z, bv0.w, bv1.x, bv1.y, bv1.z, bv1.w};
            #pragma unroll
            for (int i = 0; i < 8; i++)
                #pragma unroll
                for (int j = 0; j < 8; j++) acc[i][j] += a[i] * bb[j];
        }
    }
    #pragma unroll
    for (int i = 0; i < 8; i++) {
        long long rbase = (long long)(ty * 8 + i) * D_ + colBase + tx * 8;
        #pragma unroll
        for (int j = 0; j < 8; j += 2) {
            *(__half2*)(Cp + rbase + j) =
                __halves2half2(__float2half(acc[i][j]), __float2half(acc[i][j+1]));
        }
    }
}

__global__ __launch_bounds__(256) void attn_gram_kernel()
{
    int z = blockIdx.x, split = blockIdx.y;
    int b = z >> 4, h = z & 15;
    const float* Qb = g_X + (long long)b * S_ * D3_ + (long long)h * DH_;
    const float* Kb = Qb + D_;
    __shared__ float Qs[32][DH_];
    __shared__ float Ks[32][DH_];
    int tid = threadIdx.x, tx = tid & 15, ty = tid >> 4;
    int r = tid >> 3, c = (tid & 7) << 4;
    float acc[8][8];
    #pragma unroll
    for (int i = 0; i < 8; i++) {
        #pragma unroll
        for (int j = 0; j < 8; j++) acc[i][j] = 0.0f;
    }
    int s_begin = split * 256;
    for (int s0 = s_begin; s0 < s_begin + 256; s0 += 32) {
        __syncthreads();
        long long rowOff = (long long)(s0 + r) * D3_;
        #pragma unroll
        for (int i = 0; i < 4; i++) {
            *(float4*)&Qs[r][c + 4*i] = *(const float4*)&Qb[rowOff + c + 4*i];
            *(float4*)&Ks[r][c + 4*i] = *(const float4*)&Kb[rowOff + c + 4*i];
        }
        __syncthreads();
        #pragma unroll
        for (int kk = 0; kk < 32; kk++) {
            float4 av0 = *(const float4*)&Qs[kk][ty*8];
            float4 av1 = *(const float4*)&Qs[kk][ty*8+4];
            float4 bv0 = *(const float4*)&Ks[kk][tx*8];
            float4 bv1 = *(const float4*)&Ks[kk][tx*8+4];
            float a[8] = {av0.x,av0.y,av0.z,av0.w,av1.x,av1.y,av1.z,av1.w};
            float bb[8] = {bv0.x,bv0.y,bv0.z,bv0.w,bv1.x,bv1.y,bv1.z,bv1.w};
            #pragma unroll
            for (int i = 0; i < 8; i++)
                #pragma unroll
                for (int j = 0; j < 8; j++) acc[i][j] += a[i] * bb[j];
        }
    }
    #pragma unroll
    for (int i = 0; i < 8; i++) {
        int d = ty * 8 + i;
        *(float4*)&g_WsmP[split][z][d*DH_ + tx*8]   = make_float4(acc[i][0],acc[i][1],acc[i][2],acc[i][3]);
        *(float4*)&g_WsmP[split][z][d*DH_ + tx*8+4] = make_float4(acc[i][4],acc[i][5],acc[i][6],acc[i][7]);
    }
}

__global__ void softmax_kernel()
{
    int row = blockIdx.x;
    int z = row >> 7, d = row & 127;
    int e = threadIdx.x;
    float v = 0.0f;
    #pragma unroll
    for (int p = 0; p < 8; p++) v += g_WsmP[p][z][d*DH_ + e];
    v *= 0.022097086912079608f;
    __shared__ float red[128];
    red[e] = v; __syncthreads();
    for (int off = 64; off; off >>= 1) { if (e < off) red[e] = fmaxf(red[e], red[e+off]); __syncthreads(); }
    float mx = red[0];
    __syncthreads();
    float ex = __expf(v - mx);
    red[e] = ex; __syncthreads();
    for (int off = 64; off; off >>= 1) { if (e < off) red[e] += red[e+off]; __syncthreads(); }
    g_Wsm[z][d*DH_ + e] = ex / red[0];
}

// finalize mean / inv_std from per-CTA partials
__global__ void reduce2_kernel(double n, int nparts)
{
    int t = threadIdx.x;
    double s = 0.0, ss = 0.0;
    for (int i = t; i < nparts; i += 256) { s += g_part[2*i]; ss += g_part[2*i+1]; }
    __shared__ double shs[256], shq[256];
    shs[t] = s; shq[t] = ss; __syncthreads();
    for (int off = 128; off; off >>= 1) {
        if (t < off) { shs[t] += shs[t+off]; shq[t] += shq[t+off]; }
        __syncthreads();
    }
    if (t == 0) {
        double mean = shs[0] / n;
        double var  = (shq[0] - n * mean * mean) / (n - 1.0);
        g_stats[0] = (float)mean;
        g_stats[1] = (float)(1.0 / sqrt(var + 1e-12));
    }
}

// LN apply -> fp16 operand + fp32 residual copy
__global__ void ln_apply_dual_kernel(const float* __restrict__ x, const float* __restrict__ w,
                                     const float* __restrict__ bb, __half* __restrict__ y16,
                                     float* __restrict__ yf, long long n)
{
    float mean = g_stats[0], inv = g_stats[1];
    for (long long i = (long long)blockIdx.x * blockDim.x + threadIdx.x; i < n;
         i += (long long)gridDim.x * blockDim.x) {
        int col = (int)(i & (D_ - 1));
        float v = (x[i] - mean) * inv * w[col] + bb[col];
        y16[i] = __float2half(v);
        yf[i]  = v;
    }
}

// LN apply -> fp32 (final output)
__global__ void ln_apply_f_kernel(const float* __restrict__ x, const float* __restrict__ w,
                                  const float* __restrict__ bb, float* __restrict__ y, long long n)
{
    float mean = g_stats[0], inv = g_stats[1];
    for (long long i = (long long)blockIdx.x * blockDim.x + threadIdx.x; i < n;
         i += (long long)gridDim.x * blockDim.x) {
        int col = (int)(i & (D_ - 1));
        y[i] = (x[i] - mean) * inv * w[col] + bb[col];
    }
}

// ================= launcher =================
extern "C" void kernel_launch(void* const* d_in, const int* in_sizes, int n_in,
                              void* d_out, int out_size)
{
    const float* x      = (const float*)d_in[0];
    const float* W1_w   = (const float*)d_in[1];
    const float* W1_b   = (const float*)d_in[2];
    const float* W2_w   = (const float*)d_in[3];
    const float* W2_b   = (const float*)d_in[4];
    const float* fc_w   = (const float*)d_in[5];
    const float* fc_b   = (const float*)d_in[6];
    const float* proj_w = (const float*)d_in[7];
    const float* proj_b = (const float*)d_in[8];
    const float* ln1_w  = (const float*)d_in[9];
    const float* ln1_b  = (const float*)d_in[10];
    const float* ln2_w  = (const float*)d_in[11];
    const float* ln2_b  = (const float*)d_in[12];
    float* out = (float*)d_out;

    float *pX, *pWsm, *pR1, *pLN1, *pR2;
    __half *px16, *pW116, *pW216, *pfc16, *ppj16, *pA16, *pL116, *pH16;
    cudaGetSymbolAddress((void**)&pX,    g_X);
    cudaGetSymbolAddress((void**)&pWsm,  g_Wsm);
    cudaGetSymbolAddress((void**)&pR1,   g_R1);
    cudaGetSymbolAddress((void**)&pLN1,  g_LN1);
    cudaGetSymbolAddress((void**)&pR2,   g_R2);
    cudaGetSymbolAddress((void**)&px16,  g_x16);
    cudaGetSymbolAddress((void**)&pW116, g_W116);
    cudaGetSymbolAddress((void**)&pW216, g_W216);
    cudaGetSymbolAddress((void**)&pfc16, g_fc16);
    cudaGetSymbolAddress((void**)&ppj16, g_pj16);
    cudaGetSymbolAddress((void**)&pA16,  g_A16);
    cudaGetSymbolAddress((void**)&pL116, g_L116);
    cudaGetSymbolAddress((void**)&pH16,  g_H16);

    cudaFuncSetAttribute(mma_gemm<false,false,false,false>, cudaFuncAttributeMaxDynamicSharedMemorySize, TCG_SMEM);
    cudaFuncSetAttribute(mma_gemm<false,true ,false,true >, cudaFuncAttributeMaxDynamicSharedMemorySize, TCG_SMEM);
    cudaFuncSetAttribute(mma_gemm<true ,false,true ,false>, cudaFuncAttributeMaxDynamicSharedMemorySize, TCG_SMEM);

    // side stream for weight converts (created once; same captured work every call)
    static cudaStream_t s2 = nullptr;
    static cudaEvent_t evFork = nullptr, evJoin = nullptr;
    if (s2 == nullptr) {
        cudaStreamCreate(&s2);
        cudaEventCreateWithFlags(&evFork, cudaEventDisableTiming);
        cudaEventCreateWithFlags(&evJoin, cudaEventDisableTiming);
    }

    const long long nLN = (long long)MTOK * D_;

    // 0a) converts needed by QKV (main stream)
    convert_h<<<2048, 256>>>(x,    px16,  (long long)MTOK * D_);
    convert_h<<<2048, 256>>>(W1_w, pW116, (long long)D3_  * D_);

    // 0b) fork: W2/fc/proj converts overlap with QKV GEMM + attention
    cudaEventRecord(evFork, 0);
    cudaStreamWaitEvent(s2, evFork, 0);
    convert_h<<<1024, 256, 0, s2>>>(W2_w,   pW216, (long long)D_   * D_);
    convert_h<<<2048, 256, 0, s2>>>(fc_w,   pfc16, (long long)DFF_ * D_);
    convert_h<<<2048, 256, 0, s2>>>(proj_w, ppj16, (long long)D_ * DFF_);
    cudaEventRecord(evJoin, s2);

    // 1) QKV: g_X = x @ W1^T + b          [8192,6144] fp32
    mma_gemm<false,false,false,false><<<dim3(D3_/128, MTOK/128), 256, TCG_SMEM>>>(
        px16, pW116, D_, W1_b, nullptr, pX, nullptr, D3_);

    // 2-3) gram + softmax
    attn_gram_kernel<<<dim3(64, 8), 256>>>();
    softmax_kernel<<<64 * DH_, 128>>>();

    // 4) A = w @ V^T -> fp16 directly
    wvT_kernel<<<dim3(D_/BN, 1, 64), 256>>>(pWsm, pX, pA16);

    // join: W2 needed from step 5 on
    cudaStreamWaitEvent(0, evJoin, 0);

    // 5) R1 = A @ W2^T + b + x   (fp32 resid; emits LN partials; 1024 CTAs)
    mma_gemm<false,true,false,true><<<dim3(D_/128, MTOK/128), 256, TCG_SMEM>>>(
        pA16, pW216, D_, W2_b, x, pR1, nullptr, D_);

    // 6) LN1: finalize stats; apply -> fp16 operand + fp32 residual
    reduce2_kernel<<<1, 256>>>((double)nLN, (D_/128) * (MTOK/128));
    ln_apply_dual_kernel<<<8192, 256>>>(pR1, ln1_w, ln1_b, pL116, pLN1, nLN);

    // 7) H16 = fp16(gelu(LN1 @ fc^T + b))   [8192,8192]
    mma_gemm<true,false,true,false><<<dim3(DFF_/128, MTOK/128), 256, TCG_SMEM>>>(
        pL116, pfc16, D_, fc_b, nullptr, nullptr, pH16, DFF_);

    // 8) R2 = H @ proj^T + b + LN1  (fp32 resid; emits LN partials)
    mma_gemm<false,true,false,true><<<dim3(D_/128, MTOK/128), 256, TCG_SMEM>>>(
        pH16, ppj16, DFF_, proj_b, pLN1, pR2, nullptr, D_);

    // 9) LN2 -> out
    reduce2_kernel<<<1, 256>>>((double)nLN, (D_/128) * (MTOK/128));
    ln_apply_f_kernel<<<8192, 256>>>(pR2, ln2_w, ln2_b, out, nLN);
}

// round 13
// speedup vs baseline: 1.1366x; 1.0027x over previous
#include <cuda_runtime.h>
#include <cuda_fp16.h>
#include <math.h>
#include <stdint.h>

// ---------------- problem constants ----------------
#define B_    4
#define S_    2048
#define D_    2048
#define H_    16
#define DH_   128
#define DFF_  8192
#define MTOK  (B_*S_)          // 8192
#define D3_   (3*D_)           // 6144

// ---------------- scratch (device globals) ----------------
__device__ float   g_X    [(size_t)MTOK * D3_];       // QKV out fp32
__device__ float   g_WsmP [8][64][DH_*DH_];           // gram split-K partials
__device__ float   g_Wsm  [64][DH_*DH_];              // softmax(w)
__device__ float   g_R1   [(size_t)MTOK * D_];
__device__ float   g_LN1  [(size_t)MTOK * D_];        // LN1 fp32 (residual source)
__device__ float   g_R2   [(size_t)MTOK * D_];
__device__ __half  g_x16  [(size_t)MTOK * D_];
__device__ __half  g_W116 [(size_t)D3_  * D_];
__device__ __half  g_W216 [(size_t)D_   * D_];
__device__ __half  g_fc16 [(size_t)DFF_ * D_];
__device__ __half  g_pj16 [(size_t)D_   * DFF_];
__device__ __half  g_A16  [(size_t)MTOK * D_];
__device__ __half  g_L116 [(size_t)MTOK * D_];
__device__ __half  g_H16  [(size_t)MTOK * DFF_];
__device__ double  g_part [2048];
__device__ float   g_stats[2];

// gelu with HW tanh.approx.f32 (sm_75+)
__device__ __forceinline__ float gelu_f(float x) {
    float u = 0.7978845608028654f * (x + 0.044715f * x * x * x);
    float t;
    asm("tanh.approx.f32 %0, %1;" : "=f"(t) : "f"(u));
    return 0.5f * x * (1.0f + t);
}

// ================= baseline-PTX helpers =================
__device__ __forceinline__ uint32_t smem_u32(const void* p) {
    uint32_t a;
    asm("{ .reg .u64 t; cvta.to.shared.u64 t, %1; cvt.u32.u64 %0, t; }" : "=r"(a) : "l"(p));
    return a;
}
__device__ __forceinline__ void cp16(uint32_t s, const void* g) {
    asm volatile("cp.async.cg.shared.global [%0], [%1], 16;" :: "r"(s), "l"(g));
}
#define CP_COMMIT() asm volatile("cp.async.commit_group;" ::: "memory")
template<int N> __device__ __forceinline__ void cp_wait() {
    asm volatile("cp.async.wait_group %0;" :: "n"(N) : "memory");
}
__device__ __forceinline__ uint32_t swz128(uint32_t off) { return off ^ ((off >> 3) & 0x70); }

#define LDSM4(r, addr) \
    asm volatile("ldmatrix.sync.aligned.m8n8.x4.shared.b16 {%0,%1,%2,%3}, [%4];" \
        : "=r"((r)[0]), "=r"((r)[1]), "=r"((r)[2]), "=r"((r)[3]) : "r"(addr))

#define MMA16816(c, a, b0, b1) \
    asm volatile("mma.sync.aligned.m16n8k16.row.col.f32.f16.f16.f32 " \
        "{%0,%1,%2,%3},{%4,%5,%6,%7},{%8,%9},{%0,%1,%2,%3};" \
        : "+f"((c)[0]), "+f"((c)[1]), "+f"((c)[2]), "+f"((c)[3]) \
        : "r"((a)[0]), "r"((a)[1]), "r"((a)[2]), "r"((a)[3]), "r"(b0), "r"(b1))

// ================= mma.sync GEMM (round-7 proven config) ======
#define NS          3
#define STAGE_BYTES 32768            // A 128x64x2 = 16K, B 128x64x2 = 16K
#define TCG_SMEM    (NS * STAGE_BYTES)

__device__ __forceinline__ void load_tile(
    const __half* __restrict__ A, const __half* __restrict__ Bw,
    uint32_t tA, uint32_t tB, long long rowA0, long long rowB0,
    long long ldg, long long k0, int tid)
{
    #pragma unroll
    for (int i = 0; i < 4; i++) {                       // A: 1024 x 16B chunks
        int q = tid + 256 * i; int r = q >> 3, c = q & 7;
        cp16(tA + swz128(r * 128 + c * 16), A + (rowA0 + r) * ldg + k0 + c * 8);
    }
    #pragma unroll
    for (int i = 0; i < 4; i++) {                       // B: 1024 x 16B chunks
        int q = tid + 256 * i; int r = q >> 3, c = q & 7;
        cp16(tB + swz128(r * 128 + c * 16), Bw + (rowB0 + r) * ldg + k0 + c * 8);
    }
}

// RES: add fp32 residual. H16: also write fp16 copy. STATS: per-CTA LN partials.
template<bool GELU, bool RES, bool H16, bool STATS>
__global__ __launch_bounds__(256, 2) void mma_gemm(
    const __half* __restrict__ A, const __half* __restrict__ Bw,
    int K, const float* __restrict__ bias, const float* __restrict__ residf,
    float* __restrict__ Cf, __half* __restrict__ C16, int N)
{
    extern __shared__ char smem[];
    const uint32_t tiles = smem_u32(smem);
    const int tid  = threadIdx.x;
    const int wid  = tid >> 5, lane = tid & 31;
    const int wm   = wid >> 1, wn = wid & 1;            // 4 M x 2 N warp grid

    const long long ldg   = K;
    const long long rowA0 = (long long)blockIdx.y * 128;
    const long long rowB0 = (long long)blockIdx.x * 128;
    const int total = K >> 6;

    float acc[2][8][4];
    #pragma unroll
    for (int i = 0; i < 2; i++)
        #pragma unroll
        for (int j = 0; j < 8; j++)
            #pragma unroll
            for (int q = 0; q < 4; q++) acc[i][j][q] = 0.0f;

    for (int s = 0; s < 2; s++) {
        load_tile(A, Bw, tiles + s * STAGE_BYTES, tiles + s * STAGE_BYTES + 16384,
                  rowA0, rowB0, ldg, (long long)s << 6, tid);
        CP_COMMIT();
    }

    for (int m = 0; m < total; m++) {
        cp_wait<1>();
        __syncthreads();
        const int s = m + 2;
        if (s < total) {
            const int slot = s % NS;
            load_tile(A, Bw, tiles + slot * STAGE_BYTES, tiles + slot * STAGE_BYTES + 16384,
                      rowA0, rowB0, ldg, (long long)s << 6, tid);
        }
        CP_COMMIT();

        const uint32_t Asm = tiles + (m % NS) * STAGE_BYTES;
        const uint32_t Bsm = Asm + 16384;
        #pragma unroll
        for (int kk = 0; kk < 4; kk++) {
            uint32_t af[2][4];
            #pragma unroll
            for (int mi = 0; mi < 2; mi++) {
                uint32_t addr = Asm + swz128((wm * 32 + mi * 16 + (lane & 15)) * 128
                                             + kk * 32 + (lane >> 4) * 16);
                LDSM4(af[mi], addr);
            }
            uint32_t bfr[4][4];
            #pragma unroll
            for (int nj = 0; nj < 4; nj++) {
                uint32_t addr = Bsm + swz128((wn * 64 + nj * 16 + (lane & 15)) * 128
                                             + kk * 32 + (lane >> 4) * 16);
                LDSM4(bfr[nj], addr);
            }
            #pragma unroll
            for (int mi = 0; mi < 2; mi++)
                #pragma unroll
                for (int nj = 0; nj < 4; nj++) {
                    MMA16816(acc[mi][2*nj],   af[mi], bfr[nj][0], bfr[nj][2]);
                    MMA16816(acc[mi][2*nj+1], af[mi], bfr[nj][1], bfr[nj][3]);
                }
        }
        __syncthreads();
    }

    // ---------------- epilogue ----------------
    float st_s = 0.0f, st_q = 0.0f;
    const long long rowT = rowA0 + wm * 32;
    const long long colT = rowB0 + wn * 64;
    #pragma unroll
    for (int mi = 0; mi < 2; mi++) {
        #pragma unroll
        for (int n8 = 0; n8 < 8; n8++) {
            const long long col = colT + n8 * 8 + (lane & 3) * 2;
            const float b0 = bias[col], b1 = bias[col + 1];
            #pragma unroll
            for (int h = 0; h < 2; h++) {
                const long long row = rowT + mi * 16 + (lane >> 2) + h * 8;
                float v0 = acc[mi][n8][2*h]     + b0;
                float v1 = acc[mi][n8][2*h + 1] + b1;
                if (RES) {
                    const float2 rv = *(const float2*)(residf + row * N + col);
                    v0 += rv.x; v1 += rv.y;
                }
                if (GELU) { v0 = gelu_f(v0); v1 = gelu_f(v1); }
                if (STATS) { st_s += v0 + v1; st_q += v0 * v0 + v1 * v1; }
                if (H16) {
                    *(__half2*)(C16 + row * N + col) =
                        __halves2half2(__float2half(v0), __float2half(v1));
                }
                if (Cf != nullptr) {
                    *(float2*)(Cf + row * N + col) = make_float2(v0, v1);
                }
            }
        }
    }
    if (STATS) {
        __syncthreads();
        double* shs = (double*)smem;
        double* shq = shs + 256;
        shs[tid] = (double)st_s; shq[tid] = (double)st_q;
        __syncthreads();
        for (int off = 128; off; off >>= 1) {
            if (tid < off) { shs[tid] += shs[tid + off]; shq[tid] += shq[tid + off]; }
            __syncthreads();
        }
        if (tid == 0) {
            int cta = blockIdx.y * gridDim.x + blockIdx.x;
            g_part[2 * cta] = shs[0];
            g_part[2 * cta + 1] = shq[0];
        }
    }
}

// ================= fp32 -> fp16 conversion =================
__global__ void convert_h(const float* __restrict__ src, __half* __restrict__ dst, long long n)
{
    for (long long i = ((long long)blockIdx.x * blockDim.x + threadIdx.x) * 4; i < n;
         i += (long long)gridDim.x * blockDim.x * 4) {
        float4 v = *(const float4*)(src + i);
        *(__half2*)(dst + i)     = __halves2half2(__float2half(v.x), __float2half(v.y));
        *(__half2*)(dst + i + 2) = __halves2half2(__float2half(v.z), __float2half(v.w));
    }
}

// ================= SIMT pieces (round-7 proven) =================
#define BN 128

// A = w @ V^T per (b,h); writes fp16 directly
__global__ __launch_bounds__(256) void wvT_kernel(const float* __restrict__ Wsm,
                                                  const float* __restrict__ X,
                                                  __half* __restrict__ C16)
{
    int z = blockIdx.z; int b = z >> 4; int h = z & 15;
    const float* Ap = Wsm + (long long)z * (DH_ * DH_);
    const float* Bp = X + (long long)b * S_ * D3_ + 2 * D_ + (long long)h * DH_;
    __half* Cp = C16 + ((long long)b * S_ + (long long)h * DH_) * D_;

    __shared__ float As[16][128 + 4];
    __shared__ float Bs[16][BN + 4];
    int tid = threadIdx.x, tx = tid & 15, ty = tid >> 4;
    long long colBase = (long long)blockIdx.x * BN;
    int lr = tid >> 2, lc = (tid & 3) << 2;
    const float* Aload = Ap + lr * DH_ + lc;
    const float* Bload = Bp + (colBase + lr) * (long long)D3_ + lc;

    float acc[8][8];
    #pragma unroll
    for (int i = 0; i < 8; i++) {
        #pragma unroll
        for (int j = 0; j < 8; j++) acc[i][j] = 0.0f;
    }

    for (int k0 = 0; k0 < DH_; k0 += 16) {
        float4 a0 = *(const float4*)(Aload + k0);
        float4 a1 = *(const float4*)(Aload + 64 * DH_ + k0);
        float4 b0 = *(const float4*)(Bload + k0);
        float4 b1 = *(const float4*)(Bload + 64LL * D3_ + k0);
        __syncthreads();
        As[lc+0][lr] = a0.x; As[lc+1][lr] = a0.y; As[lc+2][lr] = a0.z; As[lc+3][lr] = a0.w;
        As[lc+0][lr+64] = a1.x; As[lc+1][lr+64] = a1.y; As[lc+2][lr+64] = a1.z; As[lc+3][lr+64] = a1.w;
        Bs[lc+0][lr] = b0.x; Bs[lc+1][lr] = b0.y; Bs[lc+2][lr] = b0.z; Bs[lc+3][lr] = b0.w;
        Bs[lc+0][lr+64] = b1.x; Bs[lc+1][lr+64] = b1.y; Bs[lc+2][lr+64] = b1.z; Bs[lc+3][lr+64] = b1.w;
        __syncthreads();
        #pragma unroll
        for (int kk = 0; kk < 16; kk++) {
            float4 av0 = *(const float4*)&As[kk][ty * 8];
            float4 av1 = *(const float4*)&As[kk][ty * 8 + 4];
            float4 bv0 = *(const float4*)&Bs[kk][tx * 8];
            float4 bv1 = *(const float4*)&Bs[kk][tx * 8 + 4];
            float a[8] = {av0.x, av0.y, av0.z, av0.w, av1.x, av1.y, av1.z, av1.w};
            float bb[8] = {bv0.x, bv0.y, bv0.z, bv0.w, bv1.x, bv1.y, bv1.z, bv1.w};
            #pragma unroll
            for (int i = 0; i < 8; i++)
                #pragma unroll
                for (int j = 0; j < 8; j++) acc[i][j] += a[i] * bb[j];
        }
    }
    #pragma unroll
    for (int i = 0; i < 8; i++) {
        long long rbase = (long long)(ty * 8 + i) * D_ + colBase + tx * 8;
        #pragma unroll
        for (int j = 0; j < 8; j += 2) {
            *(__half2*)(Cp + rbase + j) =
                __halves2half2(__float2half(acc[i][j]), __float2half(acc[i][j+1]));
        }
    }
}

__global__ __launch_bounds__(256) void attn_gram_kernel()
{
    int z = blockIdx.x, split = blockIdx.y;
    int b = z >> 4, h = z & 15;
    const float* Qb = g_X + (long long)b * S_ * D3_ + (long long)h * DH_;
    const float* Kb = Qb + D_;
    __shared__ float Qs[32][DH_];
    __shared__ float Ks[32][DH_];
    int tid = threadIdx.x, tx = tid & 15, ty = tid >> 4;
    int r = tid >> 3, c = (tid & 7) << 4;
    float acc[8][8];
    #pragma unroll
    for (int i = 0; i < 8; i++) {
        #pragma unroll
        for (int j = 0; j < 8; j++) acc[i][j] = 0.0f;
    }
    int s_begin = split * 256;
    for (int s0 = s_begin; s0 < s_begin + 256; s0 += 32) {
        __syncthreads();
        long long rowOff = (long long)(s0 + r) * D3_;
        #pragma unroll
        for (int i = 0; i < 4; i++) {
            *(float4*)&Qs[r][c + 4*i] = *(const float4*)&Qb[rowOff + c + 4*i];
            *(float4*)&Ks[r][c + 4*i] = *(const float4*)&Kb[rowOff + c + 4*i];
        }
        __syncthreads();
        #pragma unroll
        for (int kk = 0; kk < 32; kk++) {
            float4 av0 = *(const float4*)&Qs[kk][ty*8];
            float4 av1 = *(const float4*)&Qs[kk][ty*8+4];
            float4 bv0 = *(const float4*)&Ks[kk][tx*8];
            float4 bv1 = *(const float4*)&Ks[kk][tx*8+4];
            float a[8] = {av0.x,av0.y,av0.z,av0.w,av1.x,av1.y,av1.z,av1.w};
            float bb[8] = {bv0.x,bv0.y,bv0.z,bv0.w,bv1.x,bv1.y,bv1.z,bv1.w};
            #pragma unroll
            for (int i = 0; i < 8; i++)
                #pragma unroll
                for (int j = 0; j < 8; j++) acc[i][j] += a[i] * bb[j];
        }
    }
    #pragma unroll
    for (int i = 0; i < 8; i++) {
        int d = ty * 8 + i;
        *(float4*)&g_WsmP[split][z][d*DH_ + tx*8]   = make_float4(acc[i][0],acc[i][1],acc[i][2],acc[i][3]);
        *(float4*)&g_WsmP[split][z][d*DH_ + tx*8+4] = make_float4(acc[i][4],acc[i][5],acc[i][6],acc[i][7]);
    }
}

__global__ void softmax_kernel()
{
    int row = blockIdx.x;
    int z = row >> 7, d = row & 127;
    int e = threadIdx.x;
    float v = 0.0f;
    #pragma unroll
    for (int p = 0; p < 8; p++) v += g_WsmP[p][z][d*DH_ + e];
    v *= 0.022097086912079608f;
    __shared__ float red[128];
    red[e] = v; __syncthreads();
    for (int off = 64; off; off >>= 1) { if (e < off) red[e] = fmaxf(red[e], red[e+off]); __syncthreads(); }
    float mx = red[0];
    __syncthreads();
    float ex = __expf(v - mx);
    red[e] = ex; __syncthreads();
    for (int off = 64; off; off >>= 1) { if (e < off) red[e] += red[e+off]; __syncthreads(); }
    g_Wsm[z][d*DH_ + e] = ex / red[0];
}

// finalize mean / inv_std from per-CTA partials
__global__ void reduce2_kernel(double n, int nparts)
{
    int t = threadIdx.x;
    double s = 0.0, ss = 0.0;
    for (int i = t; i < nparts; i += 256) { s += g_part[2*i]; ss += g_part[2*i+1]; }
    __shared__ double shs[256], shq[256];
    shs[t] = s; shq[t] = ss; __syncthreads();
    for (int off = 128; off; off >>= 1) {
        if (t < off) { shs[t] += shs[t+off]; shq[t] += shq[t+off]; }
        __syncthreads();
    }
    if (t == 0) {
        double mean = shs[0] / n;
        double var  = (shq[0] - n * mean * mean) / (n - 1.0);
        g_stats[0] = (float)mean;
        g_stats[1] = (float)(1.0 / sqrt(var + 1e-12));
    }
}

// LN apply -> fp16 operand + fp32 residual copy
__global__ void ln_apply_dual_kernel(const float* __restrict__ x, const float* __restrict__ w,
                                     const float* __restrict__ bb, __half* __restrict__ y16,
                                     float* __restrict__ yf, long long n)
{
    float mean = g_stats[0], inv = g_stats[1];
    for (long long i = (long long)blockIdx.x * blockDim.x + threadIdx.x; i < n;
         i += (long long)gridDim.x * blockDim.x) {
        int col = (int)(i & (D_ - 1));
        float v = (x[i] - mean) * inv * w[col] + bb[col];
        y16[i] = __float2half(v);
        yf[i]  = v;
    }
}

// LN apply -> fp32 (final output)
__global__ void ln_apply_f_kernel(const float* __restrict__ x, const float* __restrict__ w,
                                  const float* __restrict__ bb, float* __restrict__ y, long long n)
{
    float mean = g_stats[0], inv = g_stats[1];
    for (long long i = (long long)blockIdx.x * blockDim.x + threadIdx.x; i < n;
         i += (long long)gridDim.x * blockDim.x) {
        int col = (int)(i & (D_ - 1));
        y[i] = (x[i] - mean) * inv * w[col] + bb[col];
    }
}

// ================= launcher =================
extern "C" void kernel_launch(void* const* d_in, const int* in_sizes, int n_in,
                              void* d_out, int out_size)
{
    const float* x      = (const float*)d_in[0];
    const float* W1_w   = (const float*)d_in[1];
    const float* W1_b   = (const float*)d_in[2];
    const float* W2_w   = (const float*)d_in[3];
    const float* W2_b   = (const float*)d_in[4];
    const float* fc_w   = (const float*)d_in[5];
    const float* fc_b   = (const float*)d_in[6];
    const float* proj_w = (const float*)d_in[7];
    const float* proj_b = (const float*)d_in[8];
    const float* ln1_w  = (const float*)d_in[9];
    const float* ln1_b  = (const float*)d_in[10];
    const float* ln2_w  = (const float*)d_in[11];
    const float* ln2_b  = (const float*)d_in[12];
    float* out = (float*)d_out;

    float *pX, *pWsm, *pR1, *pLN1, *pR2;
    __half *px16, *pW116, *pW216, *pfc16, *ppj16, *pA16, *pL116, *pH16;
    cudaGetSymbolAddress((void**)&pX,    g_X);
    cudaGetSymbolAddress((void**)&pWsm,  g_Wsm);
    cudaGetSymbolAddress((void**)&pR1,   g_R1);
    cudaGetSymbolAddress((void**)&pLN1,  g_LN1);
    cudaGetSymbolAddress((void**)&pR2,   g_R2);
    cudaGetSymbolAddress((void**)&px16,  g_x16);
    cudaGetSymbolAddress((void**)&pW116, g_W116);
    cudaGetSymbolAddress((void**)&pW216, g_W216);
    cudaGetSymbolAddress((void**)&pfc16, g_fc16);
    cudaGetSymbolAddress((void**)&ppj16, g_pj16);
    cudaGetSymbolAddress((void**)&pA16,  g_A16);
    cudaGetSymbolAddress((void**)&pL116, g_L116);
    cudaGetSymbolAddress((void**)&pH16,  g_H16);

    cudaFuncSetAttribute(mma_gemm<false,false,false,false>, cudaFuncAttributeMaxDynamicSharedMemorySize, TCG_SMEM);
    cudaFuncSetAttribute(mma_gemm<false,true ,false,true >, cudaFuncAttributeMaxDynamicSharedMemorySize, TCG_SMEM);
    cudaFuncSetAttribute(mma_gemm<true ,false,true ,false>, cudaFuncAttributeMaxDynamicSharedMemorySize, TCG_SMEM);

    // side streams/events (created once; deterministic captured work per call)
    static cudaStream_t s2 = nullptr, s3 = nullptr;
    static cudaEvent_t evFork = nullptr, evW1 = nullptr, evX = nullptr,
                       evV = nullptr, evJoin = nullptr;
    if (s2 == nullptr) {
        cudaStreamCreate(&s2);
        cudaStreamCreate(&s3);
        cudaEventCreateWithFlags(&evFork, cudaEventDisableTiming);
        cudaEventCreateWithFlags(&evW1,   cudaEventDisableTiming);
        cudaEventCreateWithFlags(&evX,    cudaEventDisableTiming);
        cudaEventCreateWithFlags(&evV,    cudaEventDisableTiming);
        cudaEventCreateWithFlags(&evJoin, cudaEventDisableTiming);
    }

    const long long nLN = (long long)MTOK * D_;

    // fork both side streams from the capture origin
    cudaEventRecord(evFork, 0);
    cudaStreamWaitEvent(s2, evFork, 0);
    cudaStreamWaitEvent(s3, evFork, 0);

    // s2: W1 convert (needed by QKV), then the late-needed weight converts
    convert_h<<<2048, 256, 0, s2>>>(W1_w, pW116, (long long)D3_ * D_);
    cudaEventRecord(evW1, s2);
    convert_h<<<1024, 256, 0, s2>>>(W2_w,   pW216, (long long)D_   * D_);
    convert_h<<<2048, 256, 0, s2>>>(fc_w,   pfc16, (long long)DFF_ * D_);
    convert_h<<<2048, 256, 0, s2>>>(proj_w, ppj16, (long long)D_ * DFF_);
    cudaEventRecord(evJoin, s2);

    // main: x convert (overlaps W1 convert)
    convert_h<<<2048, 256>>>(x, px16, (long long)MTOK * D_);
    cudaEventRecord(evX, 0);

    // s3: V slice of QKV (W1 rows 4096..6143) — independent of gram/softmax
    cudaStreamWaitEvent(s3, evW1, 0);
    cudaStreamWaitEvent(s3, evX, 0);
    mma_gemm<false,false,false,false><<<dim3(16, MTOK/128), 256, TCG_SMEM, s3>>>(
        px16, pW116 + (size_t)4096 * D_, D_, W1_b + 4096, nullptr, pX + 4096, nullptr, D3_);
    cudaEventRecord(evV, s3);

    // main: Q,K slice of QKV (W1 rows 0..4095)
    cudaStreamWaitEvent(0, evW1, 0);
    mma_gemm<false,false,false,false><<<dim3(32, MTOK/128), 256, TCG_SMEM>>>(
        px16, pW116, D_, W1_b, nullptr, pX, nullptr, D3_);

    // 2-3) gram + softmax (needs only Q,K; overlaps V-GEMM on s3)
    attn_gram_kernel<<<dim3(64, 8), 256>>>();
    softmax_kernel<<<64 * DH_, 128>>>();

    // join V before wvT
    cudaStreamWaitEvent(0, evV, 0);

    // 4) A = w @ V^T -> fp16 directly
    wvT_kernel<<<dim3(D_/BN, 1, 64), 256>>>(pWsm, pX, pA16);

    // join: W2/fc/proj needed from step 5 on
    cudaStreamWaitEvent(0, evJoin, 0);

    // 5) R1 = A @ W2^T + b + x   (fp32 resid; emits LN partials; 1024 CTAs)
    mma_gemm<false,true,false,true><<<dim3(D_/128, MTOK/128), 256, TCG_SMEM>>>(
        pA16, pW216, D_, W2_b, x, pR1, nullptr, D_);

    // 6) LN1: finalize stats; apply -> fp16 operand + fp32 residual
    reduce2_kernel<<<1, 256>>>((double)nLN, (D_/128) * (MTOK/128));
    ln_apply_dual_kernel<<<8192, 256>>>(pR1, ln1_w, ln1_b, pL116, pLN1, nLN);

    // 7) H16 = fp16(gelu(LN1 @ fc^T + b))   [8192,8192]
    mma_gemm<true,false,true,false><<<dim3(DFF_/128, MTOK/128), 256, TCG_SMEM>>>(
        pL116, pfc16, D_, fc_b, nullptr, nullptr, pH16, DFF_);

    // 8) R2 = H @ proj^T + b + LN1  (fp32 resid; emits LN partials)
    mma_gemm<false,true,false,true><<<dim3(D_/128, MTOK/128), 256, TCG_SMEM>>>(
        pH16, ppj16, DFF_, proj_b, pLN1, pR2, nullptr, D_);

    // 9) LN2 -> out
    reduce2_kernel<<<1, 256>>>((double)nLN, (D_/128) * (MTOK/128));
    ln_apply_f_kernel<<<8192, 256>>>(pR2, ln2_w, ln2_b, out, nLN);
}

// round 15
// speedup vs baseline: 1.2348x; 1.0864x over previous
#include <cuda_runtime.h>
#include <cuda_fp16.h>
#include <math.h>
#include <stdint.h>

// ---------------- problem constants ----------------
#define B_    4
#define S_    2048
#define D_    2048
#define H_    16
#define DH_   128
#define DFF_  8192
#define MTOK  (B_*S_)          // 8192
#define D3_   (3*D_)           // 6144
#define GSPL  4                // gram split-K over tokens

// ---------------- scratch (device globals) ----------------
__device__ float   g_WsmP [GSPL][64][DH_*DH_];        // gram split-K partials (fp32)
__device__ float   g_R1   [(size_t)MTOK * D_];
__device__ float   g_LN1  [(size_t)MTOK * D_];
__device__ float   g_R2   [(size_t)MTOK * D_];
__device__ __half  g_QKV16[(size_t)MTOK * D3_];       // QKV fp16 [token][6144]
__device__ __half  g_w16  [64 * DH_ * DH_];           // softmax probs fp16
__device__ __half  g_x16  [(size_t)MTOK * D_];
__device__ __half  g_W116 [(size_t)D3_  * D_];
__device__ __half  g_W216 [(size_t)D_   * D_];
__device__ __half  g_fc16 [(size_t)DFF_ * D_];
__device__ __half  g_pj16 [(size_t)D_   * DFF_];
__device__ __half  g_A16  [(size_t)MTOK * D_];
__device__ __half  g_L116 [(size_t)MTOK * D_];
__device__ __half  g_H16  [(size_t)MTOK * DFF_];
__device__ double  g_part [2048];
__device__ float   g_stats[2];

__device__ __forceinline__ float gelu_f(float x) {
    float u = 0.7978845608028654f * (x + 0.044715f * x * x * x);
    float t;
    asm("tanh.approx.f32 %0, %1;" : "=f"(t) : "f"(u));
    return 0.5f * x * (1.0f + t);
}

// ================= baseline-PTX helpers =================
__device__ __forceinline__ uint32_t smem_u32(const void* p) {
    uint32_t a;
    asm("{ .reg .u64 t; cvta.to.shared.u64 t, %1; cvt.u32.u64 %0, t; }" : "=r"(a) : "l"(p));
    return a;
}
__device__ __forceinline__ void cp16(uint32_t s, const void* g) {
    asm volatile("cp.async.cg.shared.global [%0], [%1], 16;" :: "r"(s), "l"(g));
}
#define CP_COMMIT() asm volatile("cp.async.commit_group;" ::: "memory")
template<int N> __device__ __forceinline__ void cp_wait() {
    asm volatile("cp.async.wait_group %0;" :: "n"(N) : "memory");
}
__device__ __forceinline__ uint32_t swz128(uint32_t off) { return off ^ ((off >> 3) & 0x70); }

#define LDSM4(r, addr) \
    asm volatile("ldmatrix.sync.aligned.m8n8.x4.shared.b16 {%0,%1,%2,%3}, [%4];" \
        : "=r"((r)[0]), "=r"((r)[1]), "=r"((r)[2]), "=r"((r)[3]) : "r"(addr))

#define LDSM4T(r, addr) \
    asm volatile("ldmatrix.sync.aligned.m8n8.x4.trans.shared.b16 {%0,%1,%2,%3}, [%4];" \
        : "=r"((r)[0]), "=r"((r)[1]), "=r"((r)[2]), "=r"((r)[3]) : "r"(addr))

#define MMA16816(c, a, b0, b1) \
    asm volatile("mma.sync.aligned.m16n8k16.row.col.f32.f16.f16.f32 " \
        "{%0,%1,%2,%3},{%4,%5,%6,%7},{%8,%9},{%0,%1,%2,%3};" \
        : "+f"((c)[0]), "+f"((c)[1]), "+f"((c)[2]), "+f"((c)[3]) \
        : "r"((a)[0]), "r"((a)[1]), "r"((a)[2]), "r"((a)[3]), "r"(b0), "r"(b1))

// ================= mma.sync GEMM (round-7 proven config) ======
#define NS          3
#define STAGE_BYTES 32768
#define TCG_SMEM    (NS * STAGE_BYTES)

__device__ __forceinline__ void load_tile(
    const __half* __restrict__ A, const __half* __restrict__ Bw,
    uint32_t tA, uint32_t tB, long long rowA0, long long rowB0,
    long long ldg, long long k0, int tid)
{
    #pragma unroll
    for (int i = 0; i < 4; i++) {
        int q = tid + 256 * i; int r = q >> 3, c = q & 7;
        cp16(tA + swz128(r * 128 + c * 16), A + (rowA0 + r) * ldg + k0 + c * 8);
    }
    #pragma unroll
    for (int i = 0; i < 4; i++) {
        int q = tid + 256 * i; int r = q >> 3, c = q & 7;
        cp16(tB + swz128(r * 128 + c * 16), Bw + (rowB0 + r) * ldg + k0 + c * 8);
    }
}

template<bool GELU, bool RES, bool H16, bool STATS>
__global__ __launch_bounds__(256, 2) void mma_gemm(
    const __half* __restrict__ A, const __half* __restrict__ Bw,
    int K, const float* __restrict__ bias, const float* __restrict__ residf,
    float* __restrict__ Cf, __half* __restrict__ C16, int N)
{
    extern __shared__ char smem[];
    const uint32_t tiles = smem_u32(smem);
    const int tid  = threadIdx.x;
    const int wid  = tid >> 5, lane = tid & 31;
    const int wm   = wid >> 1, wn = wid & 1;

    const long long ldg   = K;
    const long long rowA0 = (long long)blockIdx.y * 128;
    const long long rowB0 = (long long)blockIdx.x * 128;
    const int total = K >> 6;

    float acc[2][8][4];
    #pragma unroll
    for (int i = 0; i < 2; i++)
        #pragma unroll
        for (int j = 0; j < 8; j++)
            #pragma unroll
            for (int q = 0; q < 4; q++) acc[i][j][q] = 0.0f;

    for (int s = 0; s < 2; s++) {
        load_tile(A, Bw, tiles + s * STAGE_BYTES, tiles + s * STAGE_BYTES + 16384,
                  rowA0, rowB0, ldg, (long long)s << 6, tid);
        CP_COMMIT();
    }

    for (int m = 0; m < total; m++) {
        cp_wait<1>();
        __syncthreads();
        const int s = m + 2;
        if (s < total) {
            const int slot = s % NS;
            load_tile(A, Bw, tiles + slot * STAGE_BYTES, tiles + slot * STAGE_BYTES + 16384,
                      rowA0, rowB0, ldg, (long long)s << 6, tid);
        }
        CP_COMMIT();

        const uint32_t Asm = tiles + (m % NS) * STAGE_BYTES;
        const uint32_t Bsm = Asm + 16384;
        #pragma unroll
        for (int kk = 0; kk < 4; kk++) {
            uint32_t af[2][4];
            #pragma unroll
            for (int mi = 0; mi < 2; mi++) {
                uint32_t addr = Asm + swz128((wm * 32 + mi * 16 + (lane & 15)) * 128
                                             + kk * 32 + (lane >> 4) * 16);
                LDSM4(af[mi], addr);
            }
            uint32_t bfr[4][4];
            #pragma unroll
            for (int nj = 0; nj < 4; nj++) {
                uint32_t addr = Bsm + swz128((wn * 64 + nj * 16 + (lane & 15)) * 128
                                             + kk * 32 + (lane >> 4) * 16);
                LDSM4(bfr[nj], addr);
            }
            #pragma unroll
            for (int mi = 0; mi < 2; mi++)
                #pragma unroll
                for (int nj = 0; nj < 4; nj++) {
                    MMA16816(acc[mi][2*nj],   af[mi], bfr[nj][0], bfr[nj][2]);
                    MMA16816(acc[mi][2*nj+1], af[mi], bfr[nj][1], bfr[nj][3]);
                }
        }
        __syncthreads();
    }

    float st_s = 0.0f, st_q = 0.0f;
    const long long rowT = rowA0 + wm * 32;
    const long long colT = rowB0 + wn * 64;
    #pragma unroll
    for (int mi = 0; mi < 2; mi++) {
        #pragma unroll
        for (int n8 = 0; n8 < 8; n8++) {
            const long long col = colT + n8 * 8 + (lane & 3) * 2;
            const float b0 = bias[col], b1 = bias[col + 1];
            #pragma unroll
            for (int h = 0; h < 2; h++) {
                const long long row = rowT + mi * 16 + (lane >> 2) + h * 8;
                float v0 = acc[mi][n8][2*h]     + b0;
                float v1 = acc[mi][n8][2*h + 1] + b1;
                if (RES) {
                    const float2 rv = *(const float2*)(residf + row * N + col);
                    v0 += rv.x; v1 += rv.y;
                }
                if (GELU) { v0 = gelu_f(v0); v1 = gelu_f(v1); }
                if (STATS) { st_s += v0 + v1; st_q += v0 * v0 + v1 * v1; }
                if (H16) {
                    *(__half2*)(C16 + row * N + col) =
                        __halves2half2(__float2half(v0), __float2half(v1));
                }
                if (Cf != nullptr) {
                    *(float2*)(Cf + row * N + col) = make_float2(v0, v1);
                }
            }
        }
    }
    if (STATS) {
        __syncthreads();
        double* shs = (double*)smem;
        double* shq = shs + 256;
        shs[tid] = (double)st_s; shq[tid] = (double)st_q;
        __syncthreads();
        for (int off = 128; off; off >>= 1) {
            if (tid < off) { shs[tid] += shs[tid + off]; shq[tid] += shq[tid + off]; }
            __syncthreads();
        }
        if (tid == 0) {
            int cta = blockIdx.y * gridDim.x + blockIdx.x;
            g_part[2 * cta] = shs[0];
            g_part[2 * cta + 1] = shq[0];
        }
    }
}

// ================= gram via trans-ldmatrix mma ===========================
// scores[z][d][e] += sum_{s in split} Q[s,d]*K[s,e].  Tiles stored [s(64)][feat(128)]
// rows of 256B, chunk swizzle c^(r&7).  Contraction dim = smem row dim -> LDSM4T.
__global__ __launch_bounds__(256, 2) void gram_mma(const __half* __restrict__ QKV)
{
    extern __shared__ char smem[];
    const uint32_t tiles = smem_u32(smem);
    const int tid = threadIdx.x;
    const int wid = tid >> 5, lane = tid & 31;
    const int wm  = wid >> 1, wn = wid & 1;

    const int z = blockIdx.x, split = blockIdx.y;
    const int b = z >> 4, h = z & 15;
    const long long tok0 = (long long)b * S_ + split * (S_ / GSPL);
    const __half* Qb = QKV + tok0 * D3_ + h * DH_;
    const __half* Kb = Qb + D_;
    const int total = (S_ / GSPL) >> 6;              // 8 iterations of s-step 64

    float acc[2][8][4];
    #pragma unroll
    for (int i = 0; i < 2; i++)
        #pragma unroll
        for (int j = 0; j < 8; j++)
            #pragma unroll
            for (int q = 0; q < 4; q++) acc[i][j][q] = 0.0f;

    // tile loader: 64 rows x 16 chunks(16B) per operand
    auto load_g = [&](uint32_t tA, uint32_t tB, int s0) {
        #pragma unroll
        for (int i = 0; i < 4; i++) {
            int q = tid + 256 * i; int r = q >> 4, c = q & 15;
            cp16(tA + r * 256 + ((c ^ (r & 7)) * 16), Qb + (long long)(s0 + r) * D3_ + c * 8);
        }
        #pragma unroll
        for (int i = 0; i < 4; i++) {
            int q = tid + 256 * i; int r = q >> 4, c = q & 15;
            cp16(tB + r * 256 + ((c ^ (r & 7)) * 16), Kb + (long long)(s0 + r) * D3_ + c * 8);
        }
    };

    for (int s = 0; s < 2; s++) {
        load_g(tiles + s * STAGE_BYTES, tiles + s * STAGE_BYTES + 16384, s << 6);
        CP_COMMIT();
    }

    for (int m = 0; m < total; m++) {
        cp_wait<1>();
        __syncthreads();
        const int s = m + 2;
        if (s < total) {
            const int slot = s % NS;
            load_g(tiles + slot * STAGE_BYTES, tiles + slot * STAGE_BYTES + 16384, s << 6);
        }
        CP_COMMIT();

        const uint32_t Asm = tiles + (m % NS) * STAGE_BYTES;
        const uint32_t Bsm = Asm + 16384;
        const int rsel = ((lane >> 4) << 3) + (lane & 7);      // contraction row within 16
        const int csel = ((lane >> 3) & 1) << 3;               // feature col 0/8
        #pragma unroll
        for (int kk = 0; kk < 4; kk++) {
            const int sRow = kk * 16 + rsel;                   // 0..63
            uint32_t af[2][4];
            #pragma unroll
            for (int mi = 0; mi < 2; mi++) {
                int dcol = wm * 32 + mi * 16 + csel;
                int ch = (dcol >> 3) ^ (sRow & 7);
                LDSM4T(af[mi], Asm + sRow * 256 + ch * 16);
            }
            uint32_t bfr[4][4];
            #pragma unroll
            for (int nj = 0; nj < 4; nj++) {
                int ecol = wn * 64 + nj * 16 + csel;
                int ch = (ecol >> 3) ^ (sRow & 7);
                LDSM4T(bfr[nj], Bsm + sRow * 256 + ch * 16);
            }
            #pragma unroll
            for (int mi = 0; mi < 2; mi++)
                #pragma unroll
                for (int nj = 0; nj < 4; nj++) {
                    MMA16816(acc[mi][2*nj],   af[mi], bfr[nj][0], bfr[nj][2]);
                    MMA16816(acc[mi][2*nj+1], af[mi], bfr[nj][1], bfr[nj][3]);
                }
        }
        __syncthreads();
    }

    float* outp = g_WsmP[split][z];
    #pragma unroll
    for (int mi = 0; mi < 2; mi++) {
        #pragma unroll
        for (int n8 = 0; n8 < 8; n8++) {
            const int e = wn * 64 + n8 * 8 + (lane & 3) * 2;
            #pragma unroll
            for (int hh = 0; hh < 2; hh++) {
                const int d = wm * 32 + mi * 16 + (lane >> 2) + hh * 8;
                *(float2*)(outp + d * DH_ + e) =
                    make_float2(acc[mi][n8][2*hh], acc[mi][n8][2*hh+1]);
            }
        }
    }
}

// ================= wvT via mma (K-major both sides, proven in R9) =======
// A16[(b*S + h*128 + d)][ntile*128 + s] = sum_e w[d,e] V[b*S+ntile*128+s][e]
__global__ __launch_bounds__(256, 2) void wvt_mma(const __half* __restrict__ QKV)
{
    extern __shared__ char smem[];
    const uint32_t tiles = smem_u32(smem);
    const int tid = threadIdx.x;
    const int wid = tid >> 5, lane = tid & 31;
    const int wm = wid >> 1, wn = wid & 1;

    const int z = blockIdx.y, ntile = blockIdx.x;
    const int b = z >> 4, h = z & 15;
    const __half* Aw = g_w16 + (long long)z * (DH_ * DH_);
    const __half* Bv = QKV + ((long long)(b * S_ + ntile * 128)) * D3_ + 2 * D_ + h * DH_;

    float acc[2][8][4];
    #pragma unroll
    for (int i = 0; i < 2; i++)
        #pragma unroll
        for (int j = 0; j < 8; j++)
            #pragma unroll
            for (int q = 0; q < 4; q++) acc[i][j][q] = 0.0f;

    auto load_w = [&](uint32_t tA, uint32_t tB, long long k0) {
        #pragma unroll
        for (int i = 0; i < 4; i++) {
            int q = tid + 256 * i; int r = q >> 3, c = q & 7;
            cp16(tA + swz128(r * 128 + c * 16), Aw + (long long)r * DH_ + k0 + c * 8);
        }
        #pragma unroll
        for (int i = 0; i < 4; i++) {
            int q = tid + 256 * i; int r = q >> 3, c = q & 7;
            cp16(tB + swz128(r * 128 + c * 16), Bv + (long long)r * D3_ + k0 + c * 8);
        }
    };

    for (int s = 0; s < 2; s++) {
        load_w(tiles + s * STAGE_BYTES, tiles + s * STAGE_BYTES + 16384, (long long)s << 6);
        CP_COMMIT();
    }
    for (int m = 0; m < 2; m++) {
        cp_wait<1>();
        __syncthreads();
        CP_COMMIT();
        const uint32_t Asm = tiles + m * STAGE_BYTES;
        const uint32_t Bsm = Asm + 16384;
        #pragma unroll
        for (int kk = 0; kk < 4; kk++) {
            uint32_t af[2][4];
            #pragma unroll
            for (int mi = 0; mi < 2; mi++) {
                uint32_t addr = Asm + swz128((wm * 32 + mi * 16 + (lane & 15)) * 128
                                             + kk * 32 + (lane >> 4) * 16);
                LDSM4(af[mi], addr);
            }
            uint32_t bfr[4][4];
            #pragma unroll
            for (int nj = 0; nj < 4; nj++) {
                uint32_t addr = Bsm + swz128((wn * 64 + nj * 16 + (lane & 15)) * 128
                                             + kk * 32 + (lane >> 4) * 16);
                LDSM4(bfr[nj], addr);
            }
            #pragma unroll
            for (int mi = 0; mi < 2; mi++)
                #pragma unroll
                for (int nj = 0; nj < 4; nj++) {
                    MMA16816(acc[mi][2*nj],   af[mi], bfr[nj][0], bfr[nj][2]);
                    MMA16816(acc[mi][2*nj+1], af[mi], bfr[nj][1], bfr[nj][3]);
                }
        }
        __syncthreads();
    }

    const long long tB = (long long)b * S_ + h * DH_;
    #pragma unroll
    for (int mi = 0; mi < 2; mi++) {
        #pragma unroll
        for (int n8 = 0; n8 < 8; n8++) {
            const int sL = wn * 64 + n8 * 8 + (lane & 3) * 2;
            const long long f = ntile * 128 + sL;
            #pragma unroll
            for (int hh = 0; hh < 2; hh++) {
                const int d = wm * 32 + mi * 16 + (lane >> 2) + hh * 8;
                *(__half2*)(g_A16 + (tB + d) * D_ + f) =
                    __halves2half2(__float2half(acc[mi][n8][2*hh]),
                                   __float2half(acc[mi][n8][2*hh+1]));
            }
        }
    }
}

// ================= fp32 -> fp16 conversion =================
__global__ void convert_h(const float* __restrict__ src, __half* __restrict__ dst, long long n)
{
    for (long long i = ((long long)blockIdx.x * blockDim.x + threadIdx.x) * 4; i < n;
         i += (long long)gridDim.x * blockDim.x * 4) {
        float4 v = *(const float4*)(src + i);
        *(__half2*)(dst + i)     = __halves2half2(__float2half(v.x), __float2half(v.y));
        *(__half2*)(dst + i + 2) = __halves2half2(__float2half(v.z), __float2half(v.w));
    }
}

// ================= softmax over e (128), fp16 out ========================
__global__ void softmax_kernel()
{
    int row = blockIdx.x;
    int z = row >> 7, d = row & 127;
    int e = threadIdx.x;
    float v = 0.0f;
    #pragma unroll
    for (int p = 0; p < GSPL; p++) v += g_WsmP[p][z][d * DH_ + e];
    v *= 0.022097086912079608f;
    __shared__ float red[128];
    red[e] = v; __syncthreads();
    for (int off = 64; off; off >>= 1) { if (e < off) red[e] = fmaxf(red[e], red[e+off]); __syncthreads(); }
    float mx = red[0];
    __syncthreads();
    float ex = __expf(v - mx);
    red[e] = ex; __syncthreads();
    for (int off = 64; off; off >>= 1) { if (e < off) red[e] += red[e+off]; __syncthreads(); }
    g_w16[z * (DH_ * DH_) + d * DH_ + e] = __float2half(ex / red[0]);
}

__global__ void reduce2_kernel(double n, int nparts)
{
    int t = threadIdx.x;
    double s = 0.0, ss = 0.0;
    for (int i = t; i < nparts; i += 256) { s += g_part[2*i]; ss += g_part[2*i+1]; }
    __shared__ double shs[256], shq[256];
    shs[t] = s; shq[t] = ss; __syncthreads();
    for (int off = 128; off; off >>= 1) {
        if (t < off) { shs[t] += shs[t+off]; shq[t] += shq[t+off]; }
        __syncthreads();
    }
    if (t == 0) {
        double mean = shs[0] / n;
        double var  = (shq[0] - n * mean * mean) / (n - 1.0);
        g_stats[0] = (float)mean;
        g_stats[1] = (float)(1.0 / sqrt(var + 1e-12));
    }
}

__global__ void ln_apply_dual_kernel(const float* __restrict__ x, const float* __restrict__ w,
                                     const float* __restrict__ bb, __half* __restrict__ y16,
                                     float* __restrict__ yf, long long n)
{
    float mean = g_stats[0], inv = g_stats[1];
    for (long long i = (long long)blockIdx.x * blockDim.x + threadIdx.x; i < n;
         i += (long long)gridDim.x * blockDim.x) {
        int col = (int)(i & (D_ - 1));
        float v = (x[i] - mean) * inv * w[col] + bb[col];
        y16[i] = __float2half(v);
        yf[i]  = v;
    }
}

__global__ void ln_apply_f_kernel(const float* __restrict__ x, const float* __restrict__ w,
                                  const float* __restrict__ bb, float* __restrict__ y, long long n)
{
    float mean = g_stats[0], inv = g_stats[1];
    for (long long i = (long long)blockIdx.x * blockDim.x + threadIdx.x; i < n;
         i += (long long)gridDim.x * blockDim.x) {
        int col = (int)(i & (D_ - 1));
        y[i] = (x[i] - mean) * inv * w[col] + bb[col];
    }
}

// ================= launcher =================
extern "C" void kernel_launch(void* const* d_in, const int* in_sizes, int n_in,
                              void* d_out, int out_size)
{
    const float* x      = (const float*)d_in[0];
    const float* W1_w   = (const float*)d_in[1];
    const float* W1_b   = (const float*)d_in[2];
    const float* W2_w   = (const float*)d_in[3];
    const float* W2_b   = (const float*)d_in[4];
    const float* fc_w   = (const float*)d_in[5];
    const float* fc_b   = (const float*)d_in[6];
    const float* proj_w = (const float*)d_in[7];
    const float* proj_b = (const float*)d_in[8];
    const float* ln1_w  = (const float*)d_in[9];
    const float* ln1_b  = (const float*)d_in[10];
    const float* ln2_w  = (const float*)d_in[11];
    const float* ln2_b  = (const float*)d_in[12];
    float* out = (float*)d_out;

    float *pR1, *pLN1, *pR2;
    __half *px16, *pW116, *pW216, *pfc16, *ppj16, *pA16, *pL116, *pH16, *pQKV16;
    cudaGetSymbolAddress((void**)&pR1,    g_R1);
    cudaGetSymbolAddress((void**)&pLN1,   g_LN1);
    cudaGetSymbolAddress((void**)&pR2,    g_R2);
    cudaGetSymbolAddress((void**)&px16,   g_x16);
    cudaGetSymbolAddress((void**)&pW116,  g_W116);
    cudaGetSymbolAddress((void**)&pW216,  g_W216);
    cudaGetSymbolAddress((void**)&pfc16,  g_fc16);
    cudaGetSymbolAddress((void**)&ppj16,  g_pj16);
    cudaGetSymbolAddress((void**)&pA16,   g_A16);
    cudaGetSymbolAddress((void**)&pL116,  g_L116);
    cudaGetSymbolAddress((void**)&pH16,   g_H16);
    cudaGetSymbolAddress((void**)&pQKV16, g_QKV16);

    cudaFuncSetAttribute(mma_gemm<false,false,true ,false>, cudaFuncAttributeMaxDynamicSharedMemorySize, TCG_SMEM);
    cudaFuncSetAttribute(mma_gemm<false,true ,false,true >, cudaFuncAttributeMaxDynamicSharedMemorySize, TCG_SMEM);
    cudaFuncSetAttribute(mma_gemm<true ,false,true ,false>, cudaFuncAttributeMaxDynamicSharedMemorySize, TCG_SMEM);
    cudaFuncSetAttribute(gram_mma, cudaFuncAttributeMaxDynamicSharedMemorySize, TCG_SMEM);
    cudaFuncSetAttribute(wvt_mma,  cudaFuncAttributeMaxDynamicSharedMemorySize, TCG_SMEM);

    static cudaStream_t s2 = nullptr, s3 = nullptr;
    static cudaEvent_t evFork = nullptr, evW1 = nullptr, evX = nullptr,
                       evV = nullptr, evJoin = nullptr;
    if (s2 == nullptr) {
        cudaStreamCreate(&s2);
        cudaStreamCreate(&s3);
        cudaEventCreateWithFlags(&evFork, cudaEventDisableTiming);
        cudaEventCreateWithFlags(&evW1,   cudaEventDisableTiming);
        cudaEventCreateWithFlags(&evX,    cudaEventDisableTiming);
        cudaEventCreateWithFlags(&evV,    cudaEventDisableTiming);
        cudaEventCreateWithFlags(&evJoin, cudaEventDisableTiming);
    }

    const long long nLN = (long long)MTOK * D_;

    cudaEventRecord(evFork, 0);
    cudaStreamWaitEvent(s2, evFork, 0);
    cudaStreamWaitEvent(s3, evFork, 0);

    // s2: W1 convert first, then late-needed weights
    convert_h<<<2048, 256, 0, s2>>>(W1_w, pW116, (long long)D3_ * D_);
    cudaEventRecord(evW1, s2);
    convert_h<<<1024, 256, 0, s2>>>(W2_w,   pW216, (long long)D_   * D_);
    convert_h<<<2048, 256, 0, s2>>>(fc_w,   pfc16, (long long)DFF_ * D_);
    convert_h<<<2048, 256, 0, s2>>>(proj_w, ppj16, (long long)D_ * DFF_);
    cudaEventRecord(evJoin, s2);

    // main: x convert
    convert_h<<<2048, 256>>>(x, px16, (long long)MTOK * D_);
    cudaEventRecord(evX, 0);

    // s3: V slice of QKV (cols 4096..6143) -> QKV16
    cudaStreamWaitEvent(s3, evW1, 0);
    cudaStreamWaitEvent(s3, evX, 0);
    mma_gemm<false,false,true,false><<<dim3(16, MTOK/128), 256, TCG_SMEM, s3>>>(
        px16, pW116 + (size_t)4096 * D_, D_, W1_b + 4096, nullptr, nullptr, pQKV16 + 4096, D3_);
    cudaEventRecord(evV, s3);

    // main: Q,K slice of QKV (cols 0..4095) -> QKV16
    cudaStreamWaitEvent(0, evW1, 0);
    mma_gemm<false,false,true,false><<<dim3(32, MTOK/128), 256, TCG_SMEM>>>(
        px16, pW116, D_, W1_b, nullptr, nullptr, pQKV16, D3_);

    // gram (tensor core, split-4) + softmax -> fp16 probs
    gram_mma<<<dim3(64, GSPL), 256, TCG_SMEM>>>(pQKV16);
    softmax_kernel<<<64 * DH_, 128>>>();

    // join V, then wvT (tensor core)
    cudaStreamWaitEvent(0, evV, 0);
    wvt_mma<<<dim3(16, 64), 256, TCG_SMEM>>>(pQKV16);

    cudaStreamWaitEvent(0, evJoin, 0);

    // R1 = A @ W2^T + b + x
    mma_gemm<false,true,false,true><<<dim3(D_/128, MTOK/128), 256, TCG_SMEM>>>(
        pA16, pW216, D_, W2_b, x, pR1, nullptr, D_);

    // LN1
    reduce2_kernel<<<1, 256>>>((double)nLN, (D_/128) * (MTOK/128));
    ln_apply_dual_kernel<<<8192, 256>>>(pR1, ln1_w, ln1_b, pL116, pLN1, nLN);

    // H16 = fp16(gelu(LN1 @ fc^T + b))
    mma_gemm<true,false,true,false><<<dim3(DFF_/128, MTOK/128), 256, TCG_SMEM>>>(
        pL116, pfc16, D_, fc_b, nullptr, nullptr, pH16, DFF_);

    // R2 = H @ proj^T + b + LN1
    mma_gemm<false,true,false,true><<<dim3(D_/128, MTOK/128), 256, TCG_SMEM>>>(
        pH16, ppj16, DFF_, proj_b, pLN1, pR2, nullptr, D_);

    // LN2 -> out
    reduce2_kernel<<<1, 256>>>((double)nLN, (D_/128) * (MTOK/128));
    ln_apply_f_kernel<<<8192, 256>>>(pR2, ln2_w, ln2_b, out, nLN);
}

// round 16
// speedup vs baseline: 1.2477x; 1.0104x over previous
#include <cuda_runtime.h>
#include <cuda_fp16.h>
#include <math.h>
#include <stdint.h>

// ---------------- problem constants ----------------
#define B_    4
#define S_    2048
#define D_    2048
#define H_    16
#define DH_   128
#define DFF_  8192
#define MTOK  (B_*S_)          // 8192
#define D3_   (3*D_)           // 6144
#define GSPL  4                // gram split-K over tokens

// ---------------- scratch (device globals) ----------------
__device__ float   g_WsmP [GSPL][64][DH_*DH_];        // gram split-K partials (fp32)
__device__ float   g_R1   [(size_t)MTOK * D_];
__device__ float   g_LN1  [(size_t)MTOK * D_];
__device__ float   g_R2   [(size_t)MTOK * D_];
__device__ __half  g_QKV16[(size_t)MTOK * D3_];       // QKV fp16 [token][6144]
__device__ __half  g_w16  [64 * DH_ * DH_];           // softmax probs fp16
__device__ __half  g_x16  [(size_t)MTOK * D_];
__device__ __half  g_W116 [(size_t)D3_  * D_];
__device__ __half  g_W216 [(size_t)D_   * D_];
__device__ __half  g_fc16 [(size_t)DFF_ * D_];
__device__ __half  g_pj16 [(size_t)D_   * DFF_];
__device__ __half  g_A16  [(size_t)MTOK * D_];
__device__ __half  g_L116 [(size_t)MTOK * D_];
__device__ __half  g_H16  [(size_t)MTOK * DFF_];
__device__ double  g_part [2048];
__device__ float   g_stats[2];

__device__ __forceinline__ float gelu_f(float x) {
    float u = 0.7978845608028654f * (x + 0.044715f * x * x * x);
    float t;
    asm("tanh.approx.f32 %0, %1;" : "=f"(t) : "f"(u));
    return 0.5f * x * (1.0f + t);
}

// ================= baseline-PTX helpers =================
__device__ __forceinline__ uint32_t smem_u32(const void* p) {
    uint32_t a;
    asm("{ .reg .u64 t; cvta.to.shared.u64 t, %1; cvt.u32.u64 %0, t; }" : "=r"(a) : "l"(p));
    return a;
}
__device__ __forceinline__ void cp16(uint32_t s, const void* g) {
    asm volatile("cp.async.cg.shared.global [%0], [%1], 16;" :: "r"(s), "l"(g));
}
#define CP_COMMIT() asm volatile("cp.async.commit_group;" ::: "memory")
template<int N> __device__ __forceinline__ void cp_wait() {
    asm volatile("cp.async.wait_group %0;" :: "n"(N) : "memory");
}
__device__ __forceinline__ uint32_t swz128(uint32_t off) { return off ^ ((off >> 3) & 0x70); }

#define LDSM4(r, addr) \
    asm volatile("ldmatrix.sync.aligned.m8n8.x4.shared.b16 {%0,%1,%2,%3}, [%4];" \
        : "=r"((r)[0]), "=r"((r)[1]), "=r"((r)[2]), "=r"((r)[3]) : "r"(addr))

#define LDSM4T(r, addr) \
    asm volatile("ldmatrix.sync.aligned.m8n8.x4.trans.shared.b16 {%0,%1,%2,%3}, [%4];" \
        : "=r"((r)[0]), "=r"((r)[1]), "=r"((r)[2]), "=r"((r)[3]) : "r"(addr))

#define MMA16816(c, a, b0, b1) \
    asm volatile("mma.sync.aligned.m16n8k16.row.col.f32.f16.f16.f32 " \
        "{%0,%1,%2,%3},{%4,%5,%6,%7},{%8,%9},{%0,%1,%2,%3};" \
        : "+f"((c)[0]), "+f"((c)[1]), "+f"((c)[2]), "+f"((c)[3]) \
        : "r"((a)[0]), "r"((a)[1]), "r"((a)[2]), "r"((a)[3]), "r"(b0), "r"(b1))

// ================= mma.sync GEMM (round-7 proven config, single-sync mainloop) ======
#define NS          3
#define STAGE_BYTES 32768
#define TCG_SMEM    (NS * STAGE_BYTES)

__device__ __forceinline__ void load_tile(
    const __half* __restrict__ A, const __half* __restrict__ Bw,
    uint32_t tA, uint32_t tB, long long rowA0, long long rowB0,
    long long ldg, long long k0, int tid)
{
    #pragma unroll
    for (int i = 0; i < 4; i++) {
        int q = tid + 256 * i; int r = q >> 3, c = q & 7;
        cp16(tA + swz128(r * 128 + c * 16), A + (rowA0 + r) * ldg + k0 + c * 8);
    }
    #pragma unroll
    for (int i = 0; i < 4; i++) {
        int q = tid + 256 * i; int r = q >> 3, c = q & 7;
        cp16(tB + swz128(r * 128 + c * 16), Bw + (rowB0 + r) * ldg + k0 + c * 8);
    }
}

template<bool GELU, bool RES, bool H16, bool STATS>
__global__ __launch_bounds__(256, 2) void mma_gemm(
    const __half* __restrict__ A, const __half* __restrict__ Bw,
    int K, const float* __restrict__ bias, const float* __restrict__ residf,
    float* __restrict__ Cf, __half* __restrict__ C16, int N)
{
    extern __shared__ char smem[];
    const uint32_t tiles = smem_u32(smem);
    const int tid  = threadIdx.x;
    const int wid  = tid >> 5, lane = tid & 31;
    const int wm   = wid >> 1, wn = wid & 1;

    const long long ldg   = K;
    const long long rowA0 = (long long)blockIdx.y * 128;
    const long long rowB0 = (long long)blockIdx.x * 128;
    const int total = K >> 6;

    float acc[2][8][4];
    #pragma unroll
    for (int i = 0; i < 2; i++)
        #pragma unroll
        for (int j = 0; j < 8; j++)
            #pragma unroll
            for (int q = 0; q < 4; q++) acc[i][j][q] = 0.0f;

    for (int s = 0; s < 2; s++) {
        load_tile(A, Bw, tiles + s * STAGE_BYTES, tiles + s * STAGE_BYTES + 16384,
                  rowA0, rowB0, ldg, (long long)s << 6, tid);
        CP_COMMIT();
    }

    for (int m = 0; m < total; m++) {
        cp_wait<1>();
        __syncthreads();      // orders: prior-iter reads of slot (m+2)%3 before this iter's writes
        const int s = m + 2;
        if (s < total) {
            const int slot = s % NS;
            load_tile(A, Bw, tiles + slot * STAGE_BYTES, tiles + slot * STAGE_BYTES + 16384,
                      rowA0, rowB0, ldg, (long long)s << 6, tid);
        }
        CP_COMMIT();

        const uint32_t Asm = tiles + (m % NS) * STAGE_BYTES;
        const uint32_t Bsm = Asm + 16384;
        #pragma unroll
        for (int kk = 0; kk < 4; kk++) {
            uint32_t af[2][4];
            #pragma unroll
            for (int mi = 0; mi < 2; mi++) {
                uint32_t addr = Asm + swz128((wm * 32 + mi * 16 + (lane & 15)) * 128
                                             + kk * 32 + (lane >> 4) * 16);
                LDSM4(af[mi], addr);
            }
            uint32_t bfr[4][4];
            #pragma unroll
            for (int nj = 0; nj < 4; nj++) {
                uint32_t addr = Bsm + swz128((wn * 64 + nj * 16 + (lane & 15)) * 128
                                             + kk * 32 + (lane >> 4) * 16);
                LDSM4(bfr[nj], addr);
            }
            #pragma unroll
            for (int mi = 0; mi < 2; mi++)
                #pragma unroll
                for (int nj = 0; nj < 4; nj++) {
                    MMA16816(acc[mi][2*nj],   af[mi], bfr[nj][0], bfr[nj][2]);
                    MMA16816(acc[mi][2*nj+1], af[mi], bfr[nj][1], bfr[nj][3]);
                }
        }
    }

    float st_s = 0.0f, st_q = 0.0f;
    const long long rowT = rowA0 + wm * 32;
    const long long colT = rowB0 + wn * 64;
    #pragma unroll
    for (int mi = 0; mi < 2; mi++) {
        #pragma unroll
        for (int n8 = 0; n8 < 8; n8++) {
            const long long col = colT + n8 * 8 + (lane & 3) * 2;
            const float b0 = bias[col], b1 = bias[col + 1];
            #pragma unroll
            for (int h = 0; h < 2; h++) {
                const long long row = rowT + mi * 16 + (lane >> 2) + h * 8;
                float v0 = acc[mi][n8][2*h]     + b0;
                float v1 = acc[mi][n8][2*h + 1] + b1;
                if (RES) {
                    const float2 rv = *(const float2*)(residf + row * N + col);
                    v0 += rv.x; v1 += rv.y;
                }
                if (GELU) { v0 = gelu_f(v0); v1 = gelu_f(v1); }
                if (STATS) { st_s += v0 + v1; st_q += v0 * v0 + v1 * v1; }
                if (H16) {
                    *(__half2*)(C16 + row * N + col) =
                        __halves2half2(__float2half(v0), __float2half(v1));
                }
                if (Cf != nullptr) {
                    *(float2*)(Cf + row * N + col) = make_float2(v0, v1);
                }
            }
        }
    }
    if (STATS) {
        __syncthreads();
        double* shs = (double*)smem;
        double* shq = shs + 256;
        shs[tid] = (double)st_s; shq[tid] = (double)st_q;
        __syncthreads();
        for (int off = 128; off; off >>= 1) {
            if (tid < off) { shs[tid] += shs[tid + off]; shq[tid] += shq[tid + off]; }
            __syncthreads();
        }
        if (tid == 0) {
            int cta = blockIdx.y * gridDim.x + blockIdx.x;
            g_part[2 * cta] = shs[0];
            g_part[2 * cta + 1] = shq[0];
        }
    }
}

// ================= gram via trans-ldmatrix mma (single-sync) =============
__global__ __launch_bounds__(256, 2) void gram_mma(const __half* __restrict__ QKV)
{
    extern __shared__ char smem[];
    const uint32_t tiles = smem_u32(smem);
    const int tid = threadIdx.x;
    const int wid = tid >> 5, lane = tid & 31;
    const int wm  = wid >> 1, wn = wid & 1;

    const int z = blockIdx.x, split = blockIdx.y;
    const int b = z >> 4, h = z & 15;
    const long long tok0 = (long long)b * S_ + split * (S_ / GSPL);
    const __half* Qb = QKV + tok0 * D3_ + h * DH_;
    const __half* Kb = Qb + D_;
    const int total = (S_ / GSPL) >> 6;

    float acc[2][8][4];
    #pragma unroll
    for (int i = 0; i < 2; i++)
        #pragma unroll
        for (int j = 0; j < 8; j++)
            #pragma unroll
            for (int q = 0; q < 4; q++) acc[i][j][q] = 0.0f;

    auto load_g = [&](uint32_t tA, uint32_t tB, int s0) {
        #pragma unroll
        for (int i = 0; i < 4; i++) {
            int q = tid + 256 * i; int r = q >> 4, c = q & 15;
            cp16(tA + r * 256 + ((c ^ (r & 7)) * 16), Qb + (long long)(s0 + r) * D3_ + c * 8);
        }
        #pragma unroll
        for (int i = 0; i < 4; i++) {
            int q = tid + 256 * i; int r = q >> 4, c = q & 15;
            cp16(tB + r * 256 + ((c ^ (r & 7)) * 16), Kb + (long long)(s0 + r) * D3_ + c * 8);
        }
    };

    for (int s = 0; s < 2; s++) {
        load_g(tiles + s * STAGE_BYTES, tiles + s * STAGE_BYTES + 16384, s << 6);
        CP_COMMIT();
    }

    for (int m = 0; m < total; m++) {
        cp_wait<1>();
        __syncthreads();
        const int s = m + 2;
        if (s < total) {
            const int slot = s % NS;
            load_g(tiles + slot * STAGE_BYTES, tiles + slot * STAGE_BYTES + 16384, s << 6);
        }
        CP_COMMIT();

        const uint32_t Asm = tiles + (m % NS) * STAGE_BYTES;
        const uint32_t Bsm = Asm + 16384;
        const int rsel = ((lane >> 4) << 3) + (lane & 7);
        const int csel = ((lane >> 3) & 1) << 3;
        #pragma unroll
        for (int kk = 0; kk < 4; kk++) {
            const int sRow = kk * 16 + rsel;
            uint32_t af[2][4];
            #pragma unroll
            for (int mi = 0; mi < 2; mi++) {
                int dcol = wm * 32 + mi * 16 + csel;
                int ch = (dcol >> 3) ^ (sRow & 7);
                LDSM4T(af[mi], Asm + sRow * 256 + ch * 16);
            }
            uint32_t bfr[4][4];
            #pragma unroll
            for (int nj = 0; nj < 4; nj++) {
                int ecol = wn * 64 + nj * 16 + csel;
                int ch = (ecol >> 3) ^ (sRow & 7);
                LDSM4T(bfr[nj], Bsm + sRow * 256 + ch * 16);
            }
            #pragma unroll
            for (int mi = 0; mi < 2; mi++)
                #pragma unroll
                for (int nj = 0; nj < 4; nj++) {
                    MMA16816(acc[mi][2*nj],   af[mi], bfr[nj][0], bfr[nj][2]);
                    MMA16816(acc[mi][2*nj+1], af[mi], bfr[nj][1], bfr[nj][3]);
                }
        }
    }

    float* outp = g_WsmP[split][z];
    #pragma unroll
    for (int mi = 0; mi < 2; mi++) {
        #pragma unroll
        for (int n8 = 0; n8 < 8; n8++) {
            const int e = wn * 64 + n8 * 8 + (lane & 3) * 2;
            #pragma unroll
            for (int hh = 0; hh < 2; hh++) {
                const int d = wm * 32 + mi * 16 + (lane >> 2) + hh * 8;
                *(float2*)(outp + d * DH_ + e) =
                    make_float2(acc[mi][n8][2*hh], acc[mi][n8][2*hh+1]);
            }
        }
    }
}

// ================= wvT via mma (single-sync) ============================
__global__ __launch_bounds__(256, 2) void wvt_mma(const __half* __restrict__ QKV)
{
    extern __shared__ char smem[];
    const uint32_t tiles = smem_u32(smem);
    const int tid = threadIdx.x;
    const int wid = tid >> 5, lane = tid & 31;
    const int wm = wid >> 1, wn = wid & 1;

    const int z = blockIdx.y, ntile = blockIdx.x;
    const int b = z >> 4, h = z & 15;
    const __half* Aw = g_w16 + (long long)z * (DH_ * DH_);
    const __half* Bv = QKV + ((long long)(b * S_ + ntile * 128)) * D3_ + 2 * D_ + h * DH_;

    float acc[2][8][4];
    #pragma unroll
    for (int i = 0; i < 2; i++)
        #pragma unroll
        for (int j = 0; j < 8; j++)
            #pragma unroll
            for (int q = 0; q < 4; q++) acc[i][j][q] = 0.0f;

    auto load_w = [&](uint32_t tA, uint32_t tB, long long k0) {
        #pragma unroll
        for (int i = 0; i < 4; i++) {
            int q = tid + 256 * i; int r = q >> 3, c = q & 7;
            cp16(tA + swz128(r * 128 + c * 16), Aw + (long long)r * DH_ + k0 + c * 8);
        }
        #pragma unroll
        for (int i = 0; i < 4; i++) {
            int q = tid + 256 * i; int r = q >> 3, c = q & 7;
            cp16(tB + swz128(r * 128 + c * 16), Bv + (long long)r * D3_ + k0 + c * 8);
        }
    };

    for (int s = 0; s < 2; s++) {
        load_w(tiles + s * STAGE_BYTES, tiles + s * STAGE_BYTES + 16384, (long long)s << 6);
        CP_COMMIT();
    }
    for (int m = 0; m < 2; m++) {
        cp_wait<1>();
        __syncthreads();
        CP_COMMIT();
        const uint32_t Asm = tiles + m * STAGE_BYTES;
        const uint32_t Bsm = Asm + 16384;
        #pragma unroll
        for (int kk = 0; kk < 4; kk++) {
            uint32_t af[2][4];
            #pragma unroll
            for (int mi = 0; mi < 2; mi++) {
                uint32_t addr = Asm + swz128((wm * 32 + mi * 16 + (lane & 15)) * 128
                                             + kk * 32 + (lane >> 4) * 16);
                LDSM4(af[mi], addr);
            }
            uint32_t bfr[4][4];
            #pragma unroll
            for (int nj = 0; nj < 4; nj++) {
                uint32_t addr = Bsm + swz128((wn * 64 + nj * 16 + (lane & 15)) * 128
                                             + kk * 32 + (lane >> 4) * 16);
                LDSM4(bfr[nj], addr);
            }
            #pragma unroll
            for (int mi = 0; mi < 2; mi++)
                #pragma unroll
                for (int nj = 0; nj < 4; nj++) {
                    MMA16816(acc[mi][2*nj],   af[mi], bfr[nj][0], bfr[nj][2]);
                    MMA16816(acc[mi][2*nj+1], af[mi], bfr[nj][1], bfr[nj][3]);
                }
        }
    }

    const long long tB = (long long)b * S_ + h * DH_;
    #pragma unroll
    for (int mi = 0; mi < 2; mi++) {
        #pragma unroll
        for (int n8 = 0; n8 < 8; n8++) {
            const int sL = wn * 64 + n8 * 8 + (lane & 3) * 2;
            const long long f = ntile * 128 + sL;
            #pragma unroll
            for (int hh = 0; hh < 2; hh++) {
                const int d = wm * 32 + mi * 16 + (lane >> 2) + hh * 8;
                *(__half2*)(g_A16 + (tB + d) * D_ + f) =
                    __halves2half2(__float2half(acc[mi][n8][2*hh]),
                                   __float2half(acc[mi][n8][2*hh+1]));
            }
        }
    }
}

// ================= fp32 -> fp16 conversion =================
__global__ void convert_h(const float* __restrict__ src, __half* __restrict__ dst, long long n)
{
    for (long long i = ((long long)blockIdx.x * blockDim.x + threadIdx.x) * 4; i < n;
         i += (long long)gridDim.x * blockDim.x * 4) {
        float4 v = *(const float4*)(src + i);
        *(__half2*)(dst + i)     = __halves2half2(__float2half(v.x), __float2half(v.y));
        *(__half2*)(dst + i + 2) = __halves2half2(__float2half(v.z), __float2half(v.w));
    }
}

// ================= softmax over e (128), fp16 out ========================
__global__ void softmax_kernel()
{
    int row = blockIdx.x;
    int z = row >> 7, d = row & 127;
    int e = threadIdx.x;
    float v = 0.0f;
    #pragma unroll
    for (int p = 0; p < GSPL; p++) v += g_WsmP[p][z][d * DH_ + e];
    v *= 0.022097086912079608f;
    __shared__ float red[128];
    red[e] = v; __syncthreads();
    for (int off = 64; off; off >>= 1) { if (e < off) red[e] = fmaxf(red[e], red[e+off]); __syncthreads(); }
    float mx = red[0];
    __syncthreads();
    float ex = __expf(v - mx);
    red[e] = ex; __syncthreads();
    for (int off = 64; off; off >>= 1) { if (e < off) red[e] += red[e+off]; __syncthreads(); }
    g_w16[z * (DH_ * DH_) + d * DH_ + e] = __float2half(ex / red[0]);
}

__global__ void reduce2_kernel(double n, int nparts)
{
    int t = threadIdx.x;
    double s = 0.0, ss = 0.0;
    for (int i = t; i < nparts; i += 256) { s += g_part[2*i]; ss += g_part[2*i+1]; }
    __shared__ double shs[256], shq[256];
    shs[t] = s; shq[t] = ss; __syncthreads();
    for (int off = 128; off; off >>= 1) {
        if (t < off) { shs[t] += shs[t+off]; shq[t] += shq[t+off]; }
        __syncthreads();
    }
    if (t == 0) {
        double mean = shs[0] / n;
        double var  = (shq[0] - n * mean * mean) / (n - 1.0);
        g_stats[0] = (float)mean;
        g_stats[1] = (float)(1.0 / sqrt(var + 1e-12));
    }
}

__global__ void ln_apply_dual_kernel(const float* __restrict__ x, const float* __restrict__ w,
                                     const float* __restrict__ bb, __half* __restrict__ y16,
                                     float* __restrict__ yf, long long n)
{
    float mean = g_stats[0], inv = g_stats[1];
    for (long long i = (long long)blockIdx.x * blockDim.x + threadIdx.x; i < n;
         i += (long long)gridDim.x * blockDim.x) {
        int col = (int)(i & (D_ - 1));
        float v = (x[i] - mean) * inv * w[col] + bb[col];
        y16[i] = __float2half(v);
        yf[i]  = v;
    }
}

__global__ void ln_apply_f_kernel(const float* __restrict__ x, const float* __restrict__ w,
                                  const float* __restrict__ bb, float* __restrict__ y, long long n)
{
    float mean = g_stats[0], inv = g_stats[1];
    for (long long i = (long long)blockIdx.x * blockDim.x + threadIdx.x; i < n;
         i += (long long)gridDim.x * blockDim.x) {
        int col = (int)(i & (D_ - 1));
        y[i] = (x[i] - mean) * inv * w[col] + bb[col];
    }
}

// ================= launcher =================
extern "C" void kernel_launch(void* const* d_in, const int* in_sizes, int n_in,
                              void* d_out, int out_size)
{
    const float* x      = (const float*)d_in[0];
    const float* W1_w   = (const float*)d_in[1];
    const float* W1_b   = (const float*)d_in[2];
    const float* W2_w   = (const float*)d_in[3];
    const float* W2_b   = (const float*)d_in[4];
    const float* fc_w   = (const float*)d_in[5];
    const float* fc_b   = (const float*)d_in[6];
    const float* proj_w = (const float*)d_in[7];
    const float* proj_b = (const float*)d_in[8];
    const float* ln1_w  = (const float*)d_in[9];
    const float* ln1_b  = (const float*)d_in[10];
    const float* ln2_w  = (const float*)d_in[11];
    const float* ln2_b  = (const float*)d_in[12];
    float* out = (float*)d_out;

    float *pR1, *pLN1, *pR2;
    __half *px16, *pW116, *pW216, *pfc16, *ppj16, *pA16, *pL116, *pH16, *pQKV16;
    cudaGetSymbolAddress((void**)&pR1,    g_R1);
    cudaGetSymbolAddress((void**)&pLN1,   g_LN1);
    cudaGetSymbolAddress((void**)&pR2,    g_R2);
    cudaGetSymbolAddress((void**)&px16,   g_x16);
    cudaGetSymbolAddress((void**)&pW116,  g_W116);
    cudaGetSymbolAddress((void**)&pW216,  g_W216);
    cudaGetSymbolAddress((void**)&pfc16,  g_fc16);
    cudaGetSymbolAddress((void**)&ppj16,  g_pj16);
    cudaGetSymbolAddress((void**)&pA16,   g_A16);
    cudaGetSymbolAddress((void**)&pL116,  g_L116);
    cudaGetSymbolAddress((void**)&pH16,   g_H16);
    cudaGetSymbolAddress((void**)&pQKV16, g_QKV16);

    cudaFuncSetAttribute(mma_gemm<false,false,true ,false>, cudaFuncAttributeMaxDynamicSharedMemorySize, TCG_SMEM);
    cudaFuncSetAttribute(mma_gemm<false,true ,false,true >, cudaFuncAttributeMaxDynamicSharedMemorySize, TCG_SMEM);
    cudaFuncSetAttribute(mma_gemm<true ,false,true ,false>, cudaFuncAttributeMaxDynamicSharedMemorySize, TCG_SMEM);
    cudaFuncSetAttribute(gram_mma, cudaFuncAttributeMaxDynamicSharedMemorySize, TCG_SMEM);
    cudaFuncSetAttribute(wvt_mma,  cudaFuncAttributeMaxDynamicSharedMemorySize, TCG_SMEM);

    static cudaStream_t s2 = nullptr, s3 = nullptr;
    static cudaEvent_t evFork = nullptr, evW1qk = nullptr, evW1v = nullptr, evX = nullptr,
                       evV = nullptr, evJoin = nullptr;
    if (s2 == nullptr) {
        cudaStreamCreate(&s2);
        cudaStreamCreate(&s3);
        cudaEventCreateWithFlags(&evFork, cudaEventDisableTiming);
        cudaEventCreateWithFlags(&evW1qk, cudaEventDisableTiming);
        cudaEventCreateWithFlags(&evW1v,  cudaEventDisableTiming);
        cudaEventCreateWithFlags(&evX,    cudaEventDisableTiming);
        cudaEventCreateWithFlags(&evV,    cudaEventDisableTiming);
        cudaEventCreateWithFlags(&evJoin, cudaEventDisableTiming);
    }

    const long long nLN = (long long)MTOK * D_;

    cudaEventRecord(evFork, 0);
    cudaStreamWaitEvent(s2, evFork, 0);
    cudaStreamWaitEvent(s3, evFork, 0);

    // s2: W1 convert split — QK rows first (gates QK GEMM), then V rows, then late weights
    convert_h<<<2048, 256, 0, s2>>>(W1_w, pW116, (long long)4096 * D_);
    cudaEventRecord(evW1qk, s2);
    convert_h<<<1024, 256, 0, s2>>>(W1_w + (size_t)4096 * D_, pW116 + (size_t)4096 * D_,
                                    (long long)2048 * D_);
    cudaEventRecord(evW1v, s2);
    convert_h<<<1024, 256, 0, s2>>>(W2_w,   pW216, (long long)D_   * D_);
    convert_h<<<2048, 256, 0, s2>>>(fc_w,   pfc16, (long long)DFF_ * D_);
    convert_h<<<2048, 256, 0, s2>>>(proj_w, ppj16, (long long)D_ * DFF_);
    cudaEventRecord(evJoin, s2);

    // main: x convert
    convert_h<<<2048, 256>>>(x, px16, (long long)MTOK * D_);
    cudaEventRecord(evX, 0);

    // s3: V slice of QKV (cols 4096..6143) -> QKV16
    cudaStreamWaitEvent(s3, evW1v, 0);
    cudaStreamWaitEvent(s3, evX, 0);
    mma_gemm<false,false,true,false><<<dim3(16, MTOK/128), 256, TCG_SMEM, s3>>>(
        px16, pW116 + (size_t)4096 * D_, D_, W1_b + 4096, nullptr, nullptr, pQKV16 + 4096, D3_);
    cudaEventRecord(evV, s3);

    // main: Q,K slice of QKV (cols 0..4095) -> QKV16
    cudaStreamWaitEvent(0, evW1qk, 0);
    mma_gemm<false,false,true,false><<<dim3(32, MTOK/128), 256, TCG_SMEM>>>(
        px16, pW116, D_, W1_b, nullptr, nullptr, pQKV16, D3_);

    // gram (tensor core, split-4) + softmax -> fp16 probs
    gram_mma<<<dim3(64, GSPL), 256, TCG_SMEM>>>(pQKV16);
    softmax_kernel<<<64 * DH_, 128>>>();

    // join V, then wvT (tensor core)
    cudaStreamWaitEvent(0, evV, 0);
    wvt_mma<<<dim3(16, 64), 256, TCG_SMEM>>>(pQKV16);

    cudaStreamWaitEvent(0, evJoin, 0);

    // R1 = A @ W2^T + b + x
    mma_gemm<false,true,false,true><<<dim3(D_/128, MTOK/128), 256, TCG_SMEM>>>(
        pA16, pW216, D_, W2_b, x, pR1, nullptr, D_);

    // LN1
    reduce2_kernel<<<1, 256>>>((double)nLN, (D_/128) * (MTOK/128));
    ln_apply_dual_kernel<<<8192, 256>>>(pR1, ln1_w, ln1_b, pL116, pLN1, nLN);

    // H16 = fp16(gelu(LN1 @ fc^T + b))
    mma_gemm<true,false,true,false><<<dim3(DFF_/128, MTOK/128), 256, TCG_SMEM>>>(
        pL116, pfc16, D_, fc_b, nullptr, nullptr, pH16, DFF_);

    // R2 = H @ proj^T + b + LN1
    mma_gemm<false,true,false,true><<<dim3(D_/128, MTOK/128), 256, TCG_SMEM>>>(
        pH16, ppj16, DFF_, proj_b, pLN1, pR2, nullptr, D_);

    // LN2 -> out
    reduce2_kernel<<<1, 256>>>((double)nLN, (D_/128) * (MTOK/128));
    ln_apply_f_kernel<<<8192, 256>>>(pR2, ln2_w, ln2_b, out, nLN);
}